// round 10
// baseline (speedup 1.0000x reference)
#include <cuda_runtime.h>
#include <cuda_bf16.h>
#include <math.h>
#include <float.h>

// Shapes (fixed): B=4, NP=4096, D_FEAT=8, N=16, DM=16, DO=8, NM=64, PNM=64
#define BIGF 99999999.0f

// ---------------- scratch (__device__ globals) ----------------------------
__device__ int   g_idx[4 * 4096 * 16];      // knn indices, ascending-distance order
__device__ float g_zpart[4 * 4096 * 64];    // per-(b,n) z partial sums
__device__ float g_zp2[4 * 64 * 64];        // stage-1 z reduction partials
__device__ float g_zm[4 * 8];               // z @ Wmz + bmz
__device__ float g_zv[4 * 64];              // z @ Wvz + bvz

// ---------------- z-mixing biases -----------------------------------------
__global__ void zmix_kernel(const float* __restrict__ z,
                            const float* __restrict__ Wmz, const float* __restrict__ bmz,
                            const float* __restrict__ Wvz, const float* __restrict__ bvz)
{
    int t = threadIdx.x;
    if (t < 256) {                        // zv: 4 batches x 64
        int b = t >> 6, j = t & 63;
        float s = bvz[j];
        #pragma unroll 8
        for (int p = 0; p < 64; p++) s = fmaf(z[b * 64 + p], Wvz[p * 64 + j], s);
        g_zv[t] = s;
    } else if (t < 288) {                 // zm: 4 batches x 8
        int q = t - 256;
        int b = q >> 3, j = q & 7;
        float s = bmz[j];
        #pragma unroll 8
        for (int p = 0; p < 64; p++) s = fmaf(z[b * 64 + p], Wmz[p * 8 + j], s);
        g_zm[q] = s;
    }
}

// ---------------- kNN: warp-per-query, single pass, packed keys -----------
// (EXACT R6 version — known 115us / rel_err 8.519306e-6; do not touch.)
#define KNN_SMEM (4096*16*2 + 4096*4)   // xs0, xs1, n2s = 147456 B

__global__ __launch_bounds__(1024, 1) void knn_kernel(const float* __restrict__ x)
{
    extern __shared__ char smem_raw[];
    float4* xs0 = (float4*)smem_raw;                        // [4096]
    float4* xs1 = (float4*)(smem_raw + 4096 * 16);          // [4096]
    float*  n2s = (float*) (smem_raw + 4096 * 32);          // [4096]

    int b  = blockIdx.x >> 7;
    int i0 = (blockIdx.x & 127) << 5;
    int tid  = threadIdx.x;
    int w    = tid >> 5;
    int lane = tid & 31;

    const float* xb = x + (b << 15);

    // stage points + exact n2 (mul + serial rn adds, matches reference)
    #pragma unroll
    for (int k = 0; k < 4; k++) {
        int p = tid + (k << 10);
        float4 a = *(const float4*)(xb + p * 8);
        float4 c = *(const float4*)(xb + p * 8 + 4);
        xs0[p] = a;
        xs1[p] = c;
        float s = __fmul_rn(a.x, a.x);
        s = __fadd_rn(s, __fmul_rn(a.y, a.y));
        s = __fadd_rn(s, __fmul_rn(a.z, a.z));
        s = __fadd_rn(s, __fmul_rn(a.w, a.w));
        s = __fadd_rn(s, __fmul_rn(c.x, c.x));
        s = __fadd_rn(s, __fmul_rn(c.y, c.y));
        s = __fadd_rn(s, __fmul_rn(c.z, c.z));
        s = __fadd_rn(s, __fmul_rn(c.w, c.w));
        n2s[p] = s;
    }
    __syncthreads();

    int i = i0 + w;                    // this warp's query
    float4 a0 = xs0[i];
    float4 a1 = xs1[i];
    float n2i = n2s[i];

    // ---- single pass: per-lane sorted top-8 of packed keys ----
    float s0 = FLT_MAX, s1 = FLT_MAX, s2 = FLT_MAX, s3 = FLT_MAX,
          s4 = FLT_MAX, s5 = FLT_MAX, s6 = FLT_MAX, s7 = FLT_MAX;
    {
        int j = lane;
        #pragma unroll 4
        for (int k = 0; k < 128; k++) {
            float4 p0 = xs0[j];
            float4 p1 = xs1[j];
            float dot = fmaf(a0.x, p0.x,
                        fmaf(a0.y, p0.y,
                        fmaf(a0.z, p0.z,
                        fmaf(a0.w, p0.w,
                        fmaf(a1.x, p1.x,
                        fmaf(a1.y, p1.y,
                        fmaf(a1.z, p1.z, a1.w * p1.w)))))));
            float d2 = fmaf(-2.0f, dot, n2i + n2s[j]);
            unsigned kb = (__float_as_uint(d2) & 0xFFFFF000u) | (unsigned)j;
            float key = (j == i || d2 <= 0.0f) ? FLT_MAX : __uint_as_float(kb);
            float tv = key, mn;
            mn = fminf(s0, tv); tv = fmaxf(s0, tv); s0 = mn;
            mn = fminf(s1, tv); tv = fmaxf(s1, tv); s1 = mn;
            mn = fminf(s2, tv); tv = fmaxf(s2, tv); s2 = mn;
            mn = fminf(s3, tv); tv = fmaxf(s3, tv); s3 = mn;
            mn = fminf(s4, tv); tv = fmaxf(s4, tv); s4 = mn;
            mn = fminf(s5, tv); tv = fmaxf(s5, tv); s5 = mn;
            mn = fminf(s6, tv); tv = fmaxf(s6, tv); s6 = mn;
            mn = fminf(s7, tv); tv = fmaxf(s7, tv); s7 = mn;
            j += 32;
        }
    }

    // ---- 19-round tournament: lane r keeps the r-th smallest key ----
    float head = s0;
    float surv = FLT_MAX;
    #pragma unroll 1
    for (int round = 0; round < 19; round++) {
        float m = head;
        m = fminf(m, __shfl_xor_sync(0xffffffffu, m, 16));
        m = fminf(m, __shfl_xor_sync(0xffffffffu, m, 8));
        m = fminf(m, __shfl_xor_sync(0xffffffffu, m, 4));
        m = fminf(m, __shfl_xor_sync(0xffffffffu, m, 2));
        m = fminf(m, __shfl_xor_sync(0xffffffffu, m, 1));
        if (round == lane) surv = m;
        unsigned bal = __ballot_sync(0xffffffffu, head == m);
        int leader = __ffs(bal) - 1;
        if (lane == leader) {
            s0 = s1; s1 = s2; s2 = s3; s3 = s4;
            s4 = s5; s5 = s6; s6 = s7; s7 = FLT_MAX;
            head = s0;
        }
    }

    // ---- exact recompute + (dist, idx) rank sort of the 19 survivors ----
    {
        bool valid = (lane < 19) && (surv != FLT_MAX);
        int j = (int)(__float_as_uint(surv) & 0xFFFu);
        unsigned long long pk = 0xffffffffffffffffull;
        if (valid) {
            float4 p0 = xs0[j];
            float4 p1 = xs1[j];
            float dot = __fmul_rn(a0.x, p0.x);
            dot = __fmaf_rn(a0.y, p0.y, dot);
            dot = __fmaf_rn(a0.z, p0.z, dot);
            dot = __fmaf_rn(a0.w, p0.w, dot);
            dot = __fmaf_rn(a1.x, p1.x, dot);
            dot = __fmaf_rn(a1.y, p1.y, dot);
            dot = __fmaf_rn(a1.z, p1.z, dot);
            dot = __fmaf_rn(a1.w, p1.w, dot);
            float d2 = __fsub_rn(__fadd_rn(n2i, n2s[j]), __fmul_rn(2.0f, dot));
            float dd = sqrtf(fmaxf(d2, 0.0f));
            if (dd == 0.0f || j == i) dd = BIGF;
            pk = ((unsigned long long)__float_as_uint(dd) << 32) | (unsigned)j;
        }
        int rank = 0;
        #pragma unroll
        for (int m = 0; m < 32; m++) {
            unsigned long long o = __shfl_sync(0xffffffffu, pk, m);
            rank += (o < pk) ? 1 : 0;
        }
        if (valid && rank < 16)
            g_idx[(b * 4096 + i) * 16 + rank] = j;
    }
}

// ---------------- features + fused matmuls: block per (b, n-pair) ---------
// 256 threads handle n0 and n0+1. Feature phase / m-matmul / xr-reduce are
// the bit-exact R6 code applied per n-half. v-matmul is j-blocked: 1 warp
// per n, lane owns outputs {2l, 2l+1} -> per-n uniform LDS.128 count halves
// (240 -> 120 warp-LDS), Wvx read as coalesced LDG.64, z-partials stored
// directly as float2 (no vpart reduce).
__global__ __launch_bounds__(256) void feat_kernel(
    const float* __restrict__ x,
    const float* __restrict__ Wm2, const float* __restrict__ bm2,
    const float* __restrict__ Wm3, const float* __restrict__ bm3,
    const float* __restrict__ Wv2, const float* __restrict__ bv2,
    const float* __restrict__ Wv3, const float* __restrict__ bv3,
    const float* __restrict__ Wmx, const float* __restrict__ bmx,
    const float* __restrict__ Wvx, const float* __restrict__ bvx,
    float* __restrict__ xout)
{
    int b  = blockIdx.x >> 11;              // 2048 blocks per batch
    int n0 = (blockIdx.x & 2047) << 1;      // even n; block covers n0, n0+1
    int t  = threadIdx.x;

    __shared__ __align__(16) float g[2][16][8];
    __shared__ __align__(16) float msm[2][15][32];
    __shared__ __align__(16) float vsm[2][15][32];
    __shared__ float mpart[2][8][8][15];    // [nn][j][slice][r]
    __shared__ float xr[2][8][15];

    // gather 2 x 16 neighbor feature vectors (1 value per thread)
    {
        int nn = t >> 7, tt = t & 127;
        int s = tt >> 3, d = tt & 7;
        int nb = g_idx[(b * 4096 + n0 + nn) * 16 + s] & 4095;
        g[nn][s][d] = x[(size_t)(b * 4096 + nb) * 8 + d];
    }

    // feature-phase role (R6 roles on tt, applied to n-half nn)
    int nn  = t >> 7;
    int tt  = t & 127;
    int c   = tt & 31;
    int mat = (tt >> 5) & 1;
    int rh  = tt >> 6;
    bool o3 = (c >= 16);
    int  k  = o3 ? (c - 16) : c;
    float w0, w1, w2 = 0.f, bb;
    if (!o3) {
        w0 = mat ? Wv2[k]      : Wm2[k];
        w1 = mat ? Wv2[16 + k] : Wm2[16 + k];
        bb = mat ? bv2[k]      : bm2[k];
    } else {
        w0 = mat ? Wv3[k]      : Wm3[k];
        w1 = mat ? Wv3[16 + k] : Wm3[16 + k];
        w2 = mat ? Wv3[32 + k] : Wm3[32 + k];
        bb = mat ? bv3[k]      : bm3[k];
    }
    __syncthreads();

    // r-invariant base: order2 p = g0*w0+b ; order3 p = g0*w0+g1*w1+b
    float p[8];
    #pragma unroll
    for (int d = 0; d < 8; d++) {
        float base = fmaf(g[nn][0][d], w0, bb);
        p[d] = o3 ? fmaf(g[nn][1][d], w1, base) : base;
    }
    float wlast = o3 ? w2 : w1;
    float* smo = mat ? &vsm[nn][0][0] : &msm[nn][0][0];

    int r0 = rh ? 8 : 0;
    int r1 = rh ? 15 : 8;
    for (int r = r0; r < r1; r++) {
        float ssum = 0.f;
        if (o3 && r == 14) {
            // tuple (0,2,3): g0*w0 + g2*w1 + g3*w2 + b
            #pragma unroll
            for (int d = 0; d < 8; d++) {
                float v = fmaf(g[nn][3][d], w2,
                          fmaf(g[nn][2][d], w1,
                          fmaf(g[nn][0][d], w0, bb)));
                ssum += fmaxf(v, 0.f);
            }
        } else {
            int a = o3 ? (r + 2) : (r + 1);
            #pragma unroll
            for (int d = 0; d < 8; d++)
                ssum += fmaxf(fmaf(g[nn][a][d], wlast, p[d]), 0.f);
        }
        smo[r * 32 + c] = ssum * 0.125f;   // mean over d (8)
    }
    __syncthreads();

    if (t < 64) {
        // ---- v-matmul: warp vn serves n0+vn; lane owns j = {2l, 2l+1} ----
        int vn = t >> 5;
        int l  = t & 31;
        int j0 = l << 1;
        float acc0[15], acc1[15];
        #pragma unroll
        for (int r = 0; r < 15; r++) { acc0[r] = 0.f; acc1[r] = 0.f; }
        #pragma unroll
        for (int k4 = 0; k4 < 32; k4 += 4) {
            float2 q0 = *(const float2*)&Wvx[(k4 + 0) * 64 + j0];
            float2 q1 = *(const float2*)&Wvx[(k4 + 1) * 64 + j0];
            float2 q2 = *(const float2*)&Wvx[(k4 + 2) * 64 + j0];
            float2 q3 = *(const float2*)&Wvx[(k4 + 3) * 64 + j0];
            #pragma unroll
            for (int r = 0; r < 15; r++) {
                float4 vv = *(const float4*)&vsm[vn][r][k4];
                acc0[r] = fmaf(vv.x, q0.x, acc0[r]);
                acc0[r] = fmaf(vv.y, q1.x, acc0[r]);
                acc0[r] = fmaf(vv.z, q2.x, acc0[r]);
                acc0[r] = fmaf(vv.w, q3.x, acc0[r]);
                acc1[r] = fmaf(vv.x, q0.y, acc1[r]);
                acc1[r] = fmaf(vv.y, q1.y, acc1[r]);
                acc1[r] = fmaf(vv.z, q2.y, acc1[r]);
                acc1[r] = fmaf(vv.w, q3.y, acc1[r]);
            }
        }
        float bias0 = bvx[j0]     + g_zv[b * 64 + j0];
        float bias1 = bvx[j0 + 1] + g_zv[b * 64 + j0 + 1];
        float sum0 = 0.f, sum1 = 0.f;
        #pragma unroll
        for (int r = 0; r < 15; r++) {
            sum0 += fmaxf(acc0[r] + bias0, 0.f);
            sum1 += fmaxf(acc1[r] + bias1, 0.f);
        }
        float2 zz = make_float2(sum0, sum1);
        *(float2*)&g_zpart[(size_t)(b * 4096 + n0 + vn) * 64 + j0] = zz;
    } else if (t < 192) {
        // ---- m-matmul (R6 scheme per n): 64 threads per n-half ----
        int q  = t - 64;
        int mn = q >> 6;
        int qq = q & 63;
        int j  = qq >> 3;
        int sl = qq & 7;
        int k0 = sl * 4;
        float q0 = Wmx[(k0 + 0) * 8 + j];
        float q1 = Wmx[(k0 + 1) * 8 + j];
        float q2 = Wmx[(k0 + 2) * 8 + j];
        float q3 = Wmx[(k0 + 3) * 8 + j];
        #pragma unroll
        for (int r = 0; r < 15; r++) {
            float4 mv = *(const float4*)&msm[mn][r][k0];
            float a = mv.x * q0;
            a = fmaf(mv.y, q1, a);
            a = fmaf(mv.z, q2, a);
            a = fmaf(mv.w, q3, a);
            mpart[mn][j][sl][r] = a;
        }
    }
    __syncthreads();

    if (t < 240) {
        int rn = t / 120, q = t % 120;
        int j = q / 15, r = q % 15;
        float s = 0.f;
        #pragma unroll
        for (int sl = 0; sl < 8; sl++) s += mpart[rn][j][sl][r];
        xr[rn][j][r] = fmaxf(s + bmx[j] + g_zm[b * 8 + j], 0.f);
    }
    __syncthreads();
    if (t < 16) {
        int on = t >> 3, j = t & 7;
        float s = 0.f;
        #pragma unroll
        for (int r = 0; r < 15; r++) s += xr[on][j][r];
        xout[(size_t)b * 32768 + (n0 + on) * 8 + j] = s * (1.f / 15.f);
    }
}

// ---------------- z reduction, two-stage ----------------------------------
__global__ __launch_bounds__(256) void zred1_kernel()
{
    int b = blockIdx.x >> 6;
    int c = blockIdx.x & 63;
    int t = threadIdx.x;
    int q = t >> 6, j = t & 63;
    const float* zp = g_zpart + ((size_t)(b * 4096 + c * 64) * 64);
    float s = 0.f;
    #pragma unroll 4
    for (int k = q * 16; k < q * 16 + 16; k++) s += zp[k * 64 + j];
    __shared__ float red[256];
    red[t] = s;
    __syncthreads();
    if (t < 64)
        g_zp2[(b * 64 + c) * 64 + t] =
            red[t] + red[t + 64] + red[t + 128] + red[t + 192];
}

__global__ __launch_bounds__(64) void zred2_kernel(float* __restrict__ out)
{
    int b = blockIdx.x;
    int j = threadIdx.x;
    float s = 0.f;
    #pragma unroll 8
    for (int c = 0; c < 64; c++) s += g_zp2[(b * 64 + c) * 64 + j];
    out[131072 + b * 64 + j] = s * (1.f / 61440.f);
}

// ---------------- launch ---------------------------------------------------
extern "C" void kernel_launch(void* const* d_in, const int* in_sizes, int n_in,
                              void* d_out, int out_size)
{
    const float* x   = (const float*)d_in[0];
    const float* z   = (const float*)d_in[1];
    const float* Wm2 = (const float*)d_in[2];
    const float* bm2 = (const float*)d_in[3];
    const float* Wm3 = (const float*)d_in[4];
    const float* bm3 = (const float*)d_in[5];
    const float* Wv2 = (const float*)d_in[6];
    const float* bv2 = (const float*)d_in[7];
    const float* Wv3 = (const float*)d_in[8];
    const float* bv3 = (const float*)d_in[9];
    const float* Wmx = (const float*)d_in[10];
    const float* bmx = (const float*)d_in[11];
    const float* Wvx = (const float*)d_in[12];
    const float* bvx = (const float*)d_in[13];
    const float* Wmz = (const float*)d_in[14];
    const float* bmz = (const float*)d_in[15];
    const float* Wvz = (const float*)d_in[16];
    const float* bvz = (const float*)d_in[17];
    float* out = (float*)d_out;

    cudaFuncSetAttribute(knn_kernel,
                         cudaFuncAttributeMaxDynamicSharedMemorySize, KNN_SMEM);

    zmix_kernel<<<1, 288>>>(z, Wmz, bmz, Wvz, bvz);
    knn_kernel<<<512, 1024, KNN_SMEM>>>(x);
    feat_kernel<<<8192, 256>>>(x,
                               Wm2, bm2, Wm3, bm3, Wv2, bv2, Wv3, bv3,
                               Wmx, bmx, Wvx, bvx, out);
    zred1_kernel<<<256, 256>>>();
    zred2_kernel<<<4, 64>>>(out);
}

// round 11
// speedup vs baseline: 1.8976x; 1.8976x over previous
#include <cuda_runtime.h>
#include <cuda_bf16.h>
#include <math.h>
#include <float.h>

// Shapes (fixed): B=4, NP=4096, D_FEAT=8, N=16, DM=16, DO=8, NM=64, PNM=64
#define BIGF 99999999.0f

// ---------------- scratch (__device__ globals) ----------------------------
__device__ int   g_idx[4 * 4096 * 16];      // knn indices, ascending-distance order
__device__ float g_zpart[4 * 4096 * 64];    // per-(b,n) z partial sums
__device__ float g_zp2[4 * 64 * 64];        // stage-1 z reduction partials
__device__ float g_zm[4 * 8];               // z @ Wmz + bmz
__device__ float g_zv[4 * 64];              // z @ Wvz + bvz

// ---------------- z-mixing biases -----------------------------------------
__global__ void zmix_kernel(const float* __restrict__ z,
                            const float* __restrict__ Wmz, const float* __restrict__ bmz,
                            const float* __restrict__ Wvz, const float* __restrict__ bvz)
{
    int t = threadIdx.x;
    if (t < 256) {                        // zv: 4 batches x 64
        int b = t >> 6, j = t & 63;
        float s = bvz[j];
        #pragma unroll 8
        for (int p = 0; p < 64; p++) s = fmaf(z[b * 64 + p], Wvz[p * 64 + j], s);
        g_zv[t] = s;
    } else if (t < 288) {                 // zm: 4 batches x 8
        int q = t - 256;
        int b = q >> 3, j = q & 7;
        float s = bmz[j];
        #pragma unroll 8
        for (int p = 0; p < 64; p++) s = fmaf(z[b * 64 + p], Wmz[p * 8 + j], s);
        g_zm[q] = s;
    }
}

// ---------------- kNN: persistent, warp-per-query, packed keys ------------
// 148 blocks (one full wave; 147KB smem -> 1 block/SM). Block = (batch b,
// range r): 37 blocks per batch, each owning a contiguous 110/111-query
// range, staged once. Per-query selection is the exact R6 code:
// key = (d2_bits & ~0xFFF) | j; per-lane sorted top-8; 19-round tournament;
// reference-exact recompute + (dist, idx) rank sort of the 19 survivors.
#define KNN_SMEM (4096*16*2 + 4096*4)   // xs0, xs1, n2s = 147456 B
#define KNN_BLOCKS 148

__global__ __launch_bounds__(1024, 1) void knn_kernel(const float* __restrict__ x)
{
    extern __shared__ char smem_raw[];
    float4* xs0 = (float4*)smem_raw;                        // [4096]
    float4* xs1 = (float4*)(smem_raw + 4096 * 16);          // [4096]
    float*  n2s = (float*) (smem_raw + 4096 * 32);          // [4096]

    int b = blockIdx.x & 3;
    int r = blockIdx.x >> 2;               // 0..36
    // contiguous query range: 4096 = 37*110 + 26 -> first 26 ranges get 111
    int qbase = r * 110 + (r < 26 ? r : 26);
    int qcnt  = 110 + (r < 26 ? 1 : 0);

    int tid  = threadIdx.x;
    int w    = tid >> 5;
    int lane = tid & 31;

    const float* xb = x + (b << 15);

    // stage points + exact n2 (mul + serial rn adds, matches reference)
    #pragma unroll
    for (int k = 0; k < 4; k++) {
        int p = tid + (k << 10);
        float4 a = *(const float4*)(xb + p * 8);
        float4 c = *(const float4*)(xb + p * 8 + 4);
        xs0[p] = a;
        xs1[p] = c;
        float s = __fmul_rn(a.x, a.x);
        s = __fadd_rn(s, __fmul_rn(a.y, a.y));
        s = __fadd_rn(s, __fmul_rn(a.z, a.z));
        s = __fadd_rn(s, __fmul_rn(a.w, a.w));
        s = __fadd_rn(s, __fmul_rn(c.x, c.x));
        s = __fadd_rn(s, __fmul_rn(c.y, c.y));
        s = __fadd_rn(s, __fmul_rn(c.z, c.z));
        s = __fadd_rn(s, __fmul_rn(c.w, c.w));
        n2s[p] = s;
    }
    __syncthreads();

    // warp-level query loop (guard is warp-uniform; shuffles stay full-mask)
    for (int q = w; q < qcnt; q += 32) {
        int i = qbase + q;
        float4 a0 = xs0[i];
        float4 a1 = xs1[i];
        float n2i = n2s[i];

        // ---- single pass: per-lane sorted top-8 of packed keys ----
        float s0 = FLT_MAX, s1 = FLT_MAX, s2 = FLT_MAX, s3 = FLT_MAX,
              s4 = FLT_MAX, s5 = FLT_MAX, s6 = FLT_MAX, s7 = FLT_MAX;
        {
            int j = lane;
            #pragma unroll 4
            for (int k = 0; k < 128; k++) {
                float4 p0 = xs0[j];
                float4 p1 = xs1[j];
                float dot = fmaf(a0.x, p0.x,
                            fmaf(a0.y, p0.y,
                            fmaf(a0.z, p0.z,
                            fmaf(a0.w, p0.w,
                            fmaf(a1.x, p1.x,
                            fmaf(a1.y, p1.y,
                            fmaf(a1.z, p1.z, a1.w * p1.w)))))));
                float d2 = fmaf(-2.0f, dot, n2i + n2s[j]);
                unsigned kb = (__float_as_uint(d2) & 0xFFFFF000u) | (unsigned)j;
                float key = (j == i || d2 <= 0.0f) ? FLT_MAX : __uint_as_float(kb);
                float tv = key, mn;
                mn = fminf(s0, tv); tv = fmaxf(s0, tv); s0 = mn;
                mn = fminf(s1, tv); tv = fmaxf(s1, tv); s1 = mn;
                mn = fminf(s2, tv); tv = fmaxf(s2, tv); s2 = mn;
                mn = fminf(s3, tv); tv = fmaxf(s3, tv); s3 = mn;
                mn = fminf(s4, tv); tv = fmaxf(s4, tv); s4 = mn;
                mn = fminf(s5, tv); tv = fmaxf(s5, tv); s5 = mn;
                mn = fminf(s6, tv); tv = fmaxf(s6, tv); s6 = mn;
                mn = fminf(s7, tv); tv = fmaxf(s7, tv); s7 = mn;
                j += 32;
            }
        }

        // ---- 19-round tournament: lane r keeps the r-th smallest key ----
        float head = s0;
        float surv = FLT_MAX;
        #pragma unroll 1
        for (int round = 0; round < 19; round++) {
            float m = head;
            m = fminf(m, __shfl_xor_sync(0xffffffffu, m, 16));
            m = fminf(m, __shfl_xor_sync(0xffffffffu, m, 8));
            m = fminf(m, __shfl_xor_sync(0xffffffffu, m, 4));
            m = fminf(m, __shfl_xor_sync(0xffffffffu, m, 2));
            m = fminf(m, __shfl_xor_sync(0xffffffffu, m, 1));
            if (round == lane) surv = m;
            unsigned bal = __ballot_sync(0xffffffffu, head == m);
            int leader = __ffs(bal) - 1;
            if (lane == leader) {
                s0 = s1; s1 = s2; s2 = s3; s3 = s4;
                s4 = s5; s5 = s6; s6 = s7; s7 = FLT_MAX;
                head = s0;
            }
        }

        // ---- exact recompute + (dist, idx) rank sort of the survivors ----
        {
            bool valid = (lane < 19) && (surv != FLT_MAX);
            int j = (int)(__float_as_uint(surv) & 0xFFFu);
            unsigned long long pk = 0xffffffffffffffffull;
            if (valid) {
                float4 p0 = xs0[j];
                float4 p1 = xs1[j];
                float dot = __fmul_rn(a0.x, p0.x);
                dot = __fmaf_rn(a0.y, p0.y, dot);
                dot = __fmaf_rn(a0.z, p0.z, dot);
                dot = __fmaf_rn(a0.w, p0.w, dot);
                dot = __fmaf_rn(a1.x, p1.x, dot);
                dot = __fmaf_rn(a1.y, p1.y, dot);
                dot = __fmaf_rn(a1.z, p1.z, dot);
                dot = __fmaf_rn(a1.w, p1.w, dot);
                float d2 = __fsub_rn(__fadd_rn(n2i, n2s[j]), __fmul_rn(2.0f, dot));
                float dd = sqrtf(fmaxf(d2, 0.0f));
                if (dd == 0.0f || j == i) dd = BIGF;
                pk = ((unsigned long long)__float_as_uint(dd) << 32) | (unsigned)j;
            }
            int rank = 0;
            #pragma unroll
            for (int m = 0; m < 32; m++) {
                unsigned long long o = __shfl_sync(0xffffffffu, pk, m);
                rank += (o < pk) ? 1 : 0;
            }
            if (valid && rank < 16)
                g_idx[(b * 4096 + i) * 16 + rank] = j;
        }
    }
}

// ---------------- features + fused matmuls: block per (b,n) ---------------
// (EXACT R6 version — known-good 76us; pinned.)
// DM=16, K = 2*DM = 32 moment columns (cols 0..15 order-2, 16..31 order-3).
__global__ __launch_bounds__(128) void feat_kernel(
    const float* __restrict__ x,
    const float* __restrict__ Wm2, const float* __restrict__ bm2,
    const float* __restrict__ Wm3, const float* __restrict__ bm3,
    const float* __restrict__ Wv2, const float* __restrict__ bv2,
    const float* __restrict__ Wv3, const float* __restrict__ bv3,
    const float* __restrict__ Wmx, const float* __restrict__ bmx,
    const float* __restrict__ Wvx, const float* __restrict__ bvx,
    float* __restrict__ xout)
{
    int b = blockIdx.x >> 12;
    int n = blockIdx.x & 4095;
    int t = threadIdx.x;

    __shared__ __align__(16) float g[16][8];
    __shared__ __align__(16) float msm[15][32];
    __shared__ __align__(16) float vsm[15][32];
    __shared__ float mpart[8][8][15];   // [j][slice][r]
    __shared__ float xr[8][15];

    // gather 16 neighbor feature vectors
    {
        int s = t >> 3, d = t & 7;
        int nb = g_idx[(b * 4096 + n) * 16 + s] & 4095;
        g[s][d] = x[(size_t)(b * 4096 + nb) * 8 + d];
    }

    // feature-phase role
    int c   = t & 31;
    int mat = (t >> 5) & 1;
    int rh  = t >> 6;
    bool o3 = (c >= 16);
    int  k  = o3 ? (c - 16) : c;
    float w0, w1, w2 = 0.f, bb;
    if (!o3) {
        w0 = mat ? Wv2[k]      : Wm2[k];
        w1 = mat ? Wv2[16 + k] : Wm2[16 + k];
        bb = mat ? bv2[k]      : bm2[k];
    } else {
        w0 = mat ? Wv3[k]      : Wm3[k];
        w1 = mat ? Wv3[16 + k] : Wm3[16 + k];
        w2 = mat ? Wv3[32 + k] : Wm3[32 + k];
        bb = mat ? bv3[k]      : bm3[k];
    }
    __syncthreads();

    // r-invariant base: order2 p = g0*w0+b ; order3 p = g0*w0+g1*w1+b
    float p[8];
    #pragma unroll
    for (int d = 0; d < 8; d++) {
        float base = fmaf(g[0][d], w0, bb);
        p[d] = o3 ? fmaf(g[1][d], w1, base) : base;
    }
    float wlast = o3 ? w2 : w1;
    float* smo = mat ? &vsm[0][0] : &msm[0][0];

    int r0 = rh ? 8 : 0;
    int r1 = rh ? 15 : 8;
    for (int r = r0; r < r1; r++) {
        float ssum = 0.f;
        if (o3 && r == 14) {
            // tuple (0,2,3): g0*w0 + g2*w1 + g3*w2 + b
            #pragma unroll
            for (int d = 0; d < 8; d++) {
                float v = fmaf(g[3][d], w2,
                          fmaf(g[2][d], w1,
                          fmaf(g[0][d], w0, bb)));
                ssum += fmaxf(v, 0.f);
            }
        } else {
            int a = o3 ? (r + 2) : (r + 1);
            #pragma unroll
            for (int d = 0; d < 8; d++)
                ssum += fmaxf(fmaf(g[a][d], wlast, p[d]), 0.f);
        }
        smo[r * 32 + c] = ssum * 0.125f;   // mean over d (8)
    }
    __syncthreads();

    if (t < 64) {
        // v-matmul: output j=t, K=32, 15 tuples
        float acc[15];
        #pragma unroll
        for (int r = 0; r < 15; r++) acc[r] = 0.f;
        #pragma unroll
        for (int k4 = 0; k4 < 32; k4 += 4) {
            float q0 = Wvx[(k4 + 0) * 64 + t];
            float q1 = Wvx[(k4 + 1) * 64 + t];
            float q2 = Wvx[(k4 + 2) * 64 + t];
            float q3 = Wvx[(k4 + 3) * 64 + t];
            #pragma unroll
            for (int r = 0; r < 15; r++) {
                float4 vv = *(const float4*)&vsm[r][k4];
                acc[r] = fmaf(vv.x, q0, acc[r]);
                acc[r] = fmaf(vv.y, q1, acc[r]);
                acc[r] = fmaf(vv.z, q2, acc[r]);
                acc[r] = fmaf(vv.w, q3, acc[r]);
            }
        }
        float bias = bvx[t] + g_zv[b * 64 + t];
        float s = 0.f;
        #pragma unroll
        for (int r = 0; r < 15; r++) s += fmaxf(acc[r] + bias, 0.f);
        g_zpart[(size_t)(b * 4096 + n) * 64 + t] = s;
    } else {
        // m-matmul: 8 outputs x 8 k-slices of 4
        int q = t - 64;
        int j = q >> 3;
        int sl = q & 7;
        int k0 = sl * 4;
        float q0 = Wmx[(k0 + 0) * 8 + j];
        float q1 = Wmx[(k0 + 1) * 8 + j];
        float q2 = Wmx[(k0 + 2) * 8 + j];
        float q3 = Wmx[(k0 + 3) * 8 + j];
        #pragma unroll
        for (int r = 0; r < 15; r++) {
            float4 mv = *(const float4*)&msm[r][k0];
            float a = mv.x * q0;
            a = fmaf(mv.y, q1, a);
            a = fmaf(mv.z, q2, a);
            a = fmaf(mv.w, q3, a);
            mpart[j][sl][r] = a;
        }
    }
    __syncthreads();

    if (t < 120) {
        int j = t / 15, r = t % 15;
        float s = 0.f;
        #pragma unroll
        for (int sl = 0; sl < 8; sl++) s += mpart[j][sl][r];
        xr[j][r] = fmaxf(s + bmx[j] + g_zm[b * 8 + j], 0.f);
    }
    __syncthreads();
    if (t < 8) {
        float s = 0.f;
        #pragma unroll
        for (int r = 0; r < 15; r++) s += xr[t][r];
        xout[(size_t)b * 32768 + n * 8 + t] = s * (1.f / 15.f);
    }
}

// ---------------- z reduction, two-stage ----------------------------------
__global__ __launch_bounds__(256) void zred1_kernel()
{
    int b = blockIdx.x >> 6;
    int c = blockIdx.x & 63;
    int t = threadIdx.x;
    int q = t >> 6, j = t & 63;
    const float* zp = g_zpart + ((size_t)(b * 4096 + c * 64) * 64);
    float s = 0.f;
    #pragma unroll 4
    for (int k = q * 16; k < q * 16 + 16; k++) s += zp[k * 64 + j];
    __shared__ float red[256];
    red[t] = s;
    __syncthreads();
    if (t < 64)
        g_zp2[(b * 64 + c) * 64 + t] =
            red[t] + red[t + 64] + red[t + 128] + red[t + 192];
}

__global__ __launch_bounds__(64) void zred2_kernel(float* __restrict__ out)
{
    int b = blockIdx.x;
    int j = threadIdx.x;
    float s = 0.f;
    #pragma unroll 8
    for (int c = 0; c < 64; c++) s += g_zp2[(b * 64 + c) * 64 + j];
    out[131072 + b * 64 + j] = s * (1.f / 61440.f);
}

// ---------------- launch ---------------------------------------------------
extern "C" void kernel_launch(void* const* d_in, const int* in_sizes, int n_in,
                              void* d_out, int out_size)
{
    const float* x   = (const float*)d_in[0];
    const float* z   = (const float*)d_in[1];
    const float* Wm2 = (const float*)d_in[2];
    const float* bm2 = (const float*)d_in[3];
    const float* Wm3 = (const float*)d_in[4];
    const float* bm3 = (const float*)d_in[5];
    const float* Wv2 = (const float*)d_in[6];
    const float* bv2 = (const float*)d_in[7];
    const float* Wv3 = (const float*)d_in[8];
    const float* bv3 = (const float*)d_in[9];
    const float* Wmx = (const float*)d_in[10];
    const float* bmx = (const float*)d_in[11];
    const float* Wvx = (const float*)d_in[12];
    const float* bvx = (const float*)d_in[13];
    const float* Wmz = (const float*)d_in[14];
    const float* bmz = (const float*)d_in[15];
    const float* Wvz = (const float*)d_in[16];
    const float* bvz = (const float*)d_in[17];
    float* out = (float*)d_out;

    cudaFuncSetAttribute(knn_kernel,
                         cudaFuncAttributeMaxDynamicSharedMemorySize, KNN_SMEM);

    zmix_kernel<<<1, 288>>>(z, Wmz, bmz, Wvz, bvz);
    knn_kernel<<<KNN_BLOCKS, 1024, KNN_SMEM>>>(x);
    feat_kernel<<<16384, 128>>>(x,
                                Wm2, bm2, Wm3, bm3, Wv2, bv2, Wv3, bv3,
                                Wmx, bmx, Wvx, bvx, out);
    zred1_kernel<<<256, 256>>>();
    zred2_kernel<<<4, 64>>>(out);
}

// round 12
// speedup vs baseline: 1.9923x; 1.0499x over previous
#include <cuda_runtime.h>
#include <cuda_bf16.h>
#include <math.h>
#include <float.h>

// Shapes (fixed): B=4, NP=4096, D_FEAT=8, N=16, DM=16, DO=8, NM=64, PNM=64
#define BIGF 99999999.0f

// ---------------- scratch (__device__ globals) ----------------------------
__device__ int   g_idx[4 * 4096 * 16];      // knn indices, ascending-distance order
__device__ float g_zpart[4 * 4096 * 64];    // per-(b,n) z partial sums
__device__ float g_zp2[4 * 64 * 64];        // stage-1 z reduction partials
__device__ float g_zm[4 * 8];               // z @ Wmz + bmz
__device__ float g_zv[4 * 64];              // z @ Wvz + bvz

// ---------------- z-mixing biases -----------------------------------------
__global__ void zmix_kernel(const float* __restrict__ z,
                            const float* __restrict__ Wmz, const float* __restrict__ bmz,
                            const float* __restrict__ Wvz, const float* __restrict__ bvz)
{
    int t = threadIdx.x;
    if (t < 256) {                        // zv: 4 batches x 64
        int b = t >> 6, j = t & 63;
        float s = bvz[j];
        #pragma unroll 8
        for (int p = 0; p < 64; p++) s = fmaf(z[b * 64 + p], Wvz[p * 64 + j], s);
        g_zv[t] = s;
    } else if (t < 288) {                 // zm: 4 batches x 8
        int q = t - 256;
        int b = q >> 3, j = q & 7;
        float s = bmz[j];
        #pragma unroll 8
        for (int p = 0; p < 64; p++) s = fmaf(z[b * 64 + p], Wmz[p * 8 + j], s);
        g_zm[q] = s;
    }
}

#define CE(a, b) { float _mn = fminf(a, b); b = fmaxf(a, b); a = _mn; }

// ---------------- kNN: persistent, warp-per-query, batched bitonic --------
// 148 blocks (one full wave). Per-lane top-8 maintained by batched bitonic
// merge: 4 candidates -> sort4 (5 CE) -> partial merge into sorted-8 (4 min;
// exact: every dropped max has >=9 elements <= it) -> bitonic clean (12 CE).
// 9.5 FMNMX/candidate vs 16 for serial insertion; identical top-8 set, so
// output is bit-identical to R6/R11. Survivors -> reference-exact recompute
// + (dist, idx) rank sort.
#define KNN_SMEM (4096*16*2 + 4096*4)   // xs0, xs1, n2s = 147456 B
#define KNN_BLOCKS 148

__global__ __launch_bounds__(1024, 1) void knn_kernel(const float* __restrict__ x)
{
    extern __shared__ char smem_raw[];
    float4* xs0 = (float4*)smem_raw;                        // [4096]
    float4* xs1 = (float4*)(smem_raw + 4096 * 16);          // [4096]
    float*  n2s = (float*) (smem_raw + 4096 * 32);          // [4096]

    int b = blockIdx.x & 3;
    int r = blockIdx.x >> 2;               // 0..36
    // contiguous query range: 4096 = 37*110 + 26 -> first 26 ranges get 111
    int qbase = r * 110 + (r < 26 ? r : 26);
    int qcnt  = 110 + (r < 26 ? 1 : 0);

    int tid  = threadIdx.x;
    int w    = tid >> 5;
    int lane = tid & 31;

    const float* xb = x + (b << 15);

    // stage points + exact n2 (mul + serial rn adds, matches reference)
    #pragma unroll
    for (int k = 0; k < 4; k++) {
        int p = tid + (k << 10);
        float4 a = *(const float4*)(xb + p * 8);
        float4 c = *(const float4*)(xb + p * 8 + 4);
        xs0[p] = a;
        xs1[p] = c;
        float s = __fmul_rn(a.x, a.x);
        s = __fadd_rn(s, __fmul_rn(a.y, a.y));
        s = __fadd_rn(s, __fmul_rn(a.z, a.z));
        s = __fadd_rn(s, __fmul_rn(a.w, a.w));
        s = __fadd_rn(s, __fmul_rn(c.x, c.x));
        s = __fadd_rn(s, __fmul_rn(c.y, c.y));
        s = __fadd_rn(s, __fmul_rn(c.z, c.z));
        s = __fadd_rn(s, __fmul_rn(c.w, c.w));
        n2s[p] = s;
    }
    __syncthreads();

    // warp-level query loop (guard is warp-uniform; shuffles stay full-mask)
    for (int q = w; q < qcnt; q += 32) {
        int i = qbase + q;
        float4 a0 = xs0[i];
        float4 a1 = xs1[i];
        float n2i = n2s[i];

        // ---- single pass: per-lane top-8 via batched bitonic merge ----
        float s0 = FLT_MAX, s1 = FLT_MAX, s2 = FLT_MAX, s3 = FLT_MAX,
              s4 = FLT_MAX, s5 = FLT_MAX, s6 = FLT_MAX, s7 = FLT_MAX;
        {
            int j = lane;
            #pragma unroll 1
            for (int kb = 0; kb < 32; kb++) {
                float bk[4];
                #pragma unroll
                for (int c4 = 0; c4 < 4; c4++) {
                    int jj = j + (c4 << 5);
                    float4 p0 = xs0[jj];
                    float4 p1 = xs1[jj];
                    float dot = fmaf(a0.x, p0.x,
                                fmaf(a0.y, p0.y,
                                fmaf(a0.z, p0.z,
                                fmaf(a0.w, p0.w,
                                fmaf(a1.x, p1.x,
                                fmaf(a1.y, p1.y,
                                fmaf(a1.z, p1.z, a1.w * p1.w)))))));
                    float d2 = fmaf(-2.0f, dot, n2i + n2s[jj]);
                    unsigned kbits = (__float_as_uint(d2) & 0xFFFFF000u) | (unsigned)jj;
                    bk[c4] = (jj == i || d2 <= 0.0f) ? FLT_MAX : __uint_as_float(kbits);
                }
                // sort4 (ascending)
                CE(bk[0], bk[1]); CE(bk[2], bk[3]);
                CE(bk[0], bk[2]); CE(bk[1], bk[3]);
                CE(bk[1], bk[2]);
                // partial bitonic merge: keep min-half (exact top-8 of union)
                s4 = fminf(s4, bk[3]);
                s5 = fminf(s5, bk[2]);
                s6 = fminf(s6, bk[1]);
                s7 = fminf(s7, bk[0]);
                // bitonic clean of 8 (result sorted ascending)
                CE(s0, s4); CE(s1, s5); CE(s2, s6); CE(s3, s7);
                CE(s0, s2); CE(s1, s3); CE(s4, s6); CE(s5, s7);
                CE(s0, s1); CE(s2, s3); CE(s4, s5); CE(s6, s7);
                j += 128;
            }
        }

        // ---- 19-round tournament: lane r keeps the r-th smallest key ----
        float head = s0;
        float surv = FLT_MAX;
        #pragma unroll 1
        for (int round = 0; round < 19; round++) {
            float m = head;
            m = fminf(m, __shfl_xor_sync(0xffffffffu, m, 16));
            m = fminf(m, __shfl_xor_sync(0xffffffffu, m, 8));
            m = fminf(m, __shfl_xor_sync(0xffffffffu, m, 4));
            m = fminf(m, __shfl_xor_sync(0xffffffffu, m, 2));
            m = fminf(m, __shfl_xor_sync(0xffffffffu, m, 1));
            if (round == lane) surv = m;
            unsigned bal = __ballot_sync(0xffffffffu, head == m);
            int leader = __ffs(bal) - 1;
            if (lane == leader) {
                s0 = s1; s1 = s2; s2 = s3; s3 = s4;
                s4 = s5; s5 = s6; s6 = s7; s7 = FLT_MAX;
                head = s0;
            }
        }

        // ---- exact recompute + (dist, idx) rank sort of the survivors ----
        {
            bool valid = (lane < 19) && (surv != FLT_MAX);
            int j = (int)(__float_as_uint(surv) & 0xFFFu);
            unsigned long long pk = 0xffffffffffffffffull;
            if (valid) {
                float4 p0 = xs0[j];
                float4 p1 = xs1[j];
                float dot = __fmul_rn(a0.x, p0.x);
                dot = __fmaf_rn(a0.y, p0.y, dot);
                dot = __fmaf_rn(a0.z, p0.z, dot);
                dot = __fmaf_rn(a0.w, p0.w, dot);
                dot = __fmaf_rn(a1.x, p1.x, dot);
                dot = __fmaf_rn(a1.y, p1.y, dot);
                dot = __fmaf_rn(a1.z, p1.z, dot);
                dot = __fmaf_rn(a1.w, p1.w, dot);
                float d2 = __fsub_rn(__fadd_rn(n2i, n2s[j]), __fmul_rn(2.0f, dot));
                float dd = sqrtf(fmaxf(d2, 0.0f));
                if (dd == 0.0f || j == i) dd = BIGF;
                pk = ((unsigned long long)__float_as_uint(dd) << 32) | (unsigned)j;
            }
            int rank = 0;
            #pragma unroll
            for (int m = 0; m < 32; m++) {
                unsigned long long o = __shfl_sync(0xffffffffu, pk, m);
                rank += (o < pk) ? 1 : 0;
            }
            if (valid && rank < 16)
                g_idx[(b * 4096 + i) * 16 + rank] = j;
        }
    }
}

// ---------------- features + fused matmuls: block per (b,n) ---------------
// (EXACT R6 version — known-good 76us; pinned.)
// DM=16, K = 2*DM = 32 moment columns (cols 0..15 order-2, 16..31 order-3).
__global__ __launch_bounds__(128) void feat_kernel(
    const float* __restrict__ x,
    const float* __restrict__ Wm2, const float* __restrict__ bm2,
    const float* __restrict__ Wm3, const float* __restrict__ bm3,
    const float* __restrict__ Wv2, const float* __restrict__ bv2,
    const float* __restrict__ Wv3, const float* __restrict__ bv3,
    const float* __restrict__ Wmx, const float* __restrict__ bmx,
    const float* __restrict__ Wvx, const float* __restrict__ bvx,
    float* __restrict__ xout)
{
    int b = blockIdx.x >> 12;
    int n = blockIdx.x & 4095;
    int t = threadIdx.x;

    __shared__ __align__(16) float g[16][8];
    __shared__ __align__(16) float msm[15][32];
    __shared__ __align__(16) float vsm[15][32];
    __shared__ float mpart[8][8][15];   // [j][slice][r]
    __shared__ float xr[8][15];

    // gather 16 neighbor feature vectors
    {
        int s = t >> 3, d = t & 7;
        int nb = g_idx[(b * 4096 + n) * 16 + s] & 4095;
        g[s][d] = x[(size_t)(b * 4096 + nb) * 8 + d];
    }

    // feature-phase role
    int c   = t & 31;
    int mat = (t >> 5) & 1;
    int rh  = t >> 6;
    bool o3 = (c >= 16);
    int  k  = o3 ? (c - 16) : c;
    float w0, w1, w2 = 0.f, bb;
    if (!o3) {
        w0 = mat ? Wv2[k]      : Wm2[k];
        w1 = mat ? Wv2[16 + k] : Wm2[16 + k];
        bb = mat ? bv2[k]      : bm2[k];
    } else {
        w0 = mat ? Wv3[k]      : Wm3[k];
        w1 = mat ? Wv3[16 + k] : Wm3[16 + k];
        w2 = mat ? Wv3[32 + k] : Wm3[32 + k];
        bb = mat ? bv3[k]      : bm3[k];
    }
    __syncthreads();

    // r-invariant base: order2 p = g0*w0+b ; order3 p = g0*w0+g1*w1+b
    float p[8];
    #pragma unroll
    for (int d = 0; d < 8; d++) {
        float base = fmaf(g[0][d], w0, bb);
        p[d] = o3 ? fmaf(g[1][d], w1, base) : base;
    }
    float wlast = o3 ? w2 : w1;
    float* smo = mat ? &vsm[0][0] : &msm[0][0];

    int r0 = rh ? 8 : 0;
    int r1 = rh ? 15 : 8;
    for (int r = r0; r < r1; r++) {
        float ssum = 0.f;
        if (o3 && r == 14) {
            // tuple (0,2,3): g0*w0 + g2*w1 + g3*w2 + b
            #pragma unroll
            for (int d = 0; d < 8; d++) {
                float v = fmaf(g[3][d], w2,
                          fmaf(g[2][d], w1,
                          fmaf(g[0][d], w0, bb)));
                ssum += fmaxf(v, 0.f);
            }
        } else {
            int a = o3 ? (r + 2) : (r + 1);
            #pragma unroll
            for (int d = 0; d < 8; d++)
                ssum += fmaxf(fmaf(g[a][d], wlast, p[d]), 0.f);
        }
        smo[r * 32 + c] = ssum * 0.125f;   // mean over d (8)
    }
    __syncthreads();

    if (t < 64) {
        // v-matmul: output j=t, K=32, 15 tuples
        float acc[15];
        #pragma unroll
        for (int r = 0; r < 15; r++) acc[r] = 0.f;
        #pragma unroll
        for (int k4 = 0; k4 < 32; k4 += 4) {
            float q0 = Wvx[(k4 + 0) * 64 + t];
            float q1 = Wvx[(k4 + 1) * 64 + t];
            float q2 = Wvx[(k4 + 2) * 64 + t];
            float q3 = Wvx[(k4 + 3) * 64 + t];
            #pragma unroll
            for (int r = 0; r < 15; r++) {
                float4 vv = *(const float4*)&vsm[r][k4];
                acc[r] = fmaf(vv.x, q0, acc[r]);
                acc[r] = fmaf(vv.y, q1, acc[r]);
                acc[r] = fmaf(vv.z, q2, acc[r]);
                acc[r] = fmaf(vv.w, q3, acc[r]);
            }
        }
        float bias = bvx[t] + g_zv[b * 64 + t];
        float s = 0.f;
        #pragma unroll
        for (int r = 0; r < 15; r++) s += fmaxf(acc[r] + bias, 0.f);
        g_zpart[(size_t)(b * 4096 + n) * 64 + t] = s;
    } else {
        // m-matmul: 8 outputs x 8 k-slices of 4
        int q = t - 64;
        int j = q >> 3;
        int sl = q & 7;
        int k0 = sl * 4;
        float q0 = Wmx[(k0 + 0) * 8 + j];
        float q1 = Wmx[(k0 + 1) * 8 + j];
        float q2 = Wmx[(k0 + 2) * 8 + j];
        float q3 = Wmx[(k0 + 3) * 8 + j];
        #pragma unroll
        for (int r = 0; r < 15; r++) {
            float4 mv = *(const float4*)&msm[r][k0];
            float a = mv.x * q0;
            a = fmaf(mv.y, q1, a);
            a = fmaf(mv.z, q2, a);
            a = fmaf(mv.w, q3, a);
            mpart[j][sl][r] = a;
        }
    }
    __syncthreads();

    if (t < 120) {
        int j = t / 15, r = t % 15;
        float s = 0.f;
        #pragma unroll
        for (int sl = 0; sl < 8; sl++) s += mpart[j][sl][r];
        xr[j][r] = fmaxf(s + bmx[j] + g_zm[b * 8 + j], 0.f);
    }
    __syncthreads();
    if (t < 8) {
        float s = 0.f;
        #pragma unroll
        for (int r = 0; r < 15; r++) s += xr[t][r];
        xout[(size_t)b * 32768 + n * 8 + t] = s * (1.f / 15.f);
    }
}

// ---------------- z reduction, two-stage ----------------------------------
__global__ __launch_bounds__(256) void zred1_kernel()
{
    int b = blockIdx.x >> 6;
    int c = blockIdx.x & 63;
    int t = threadIdx.x;
    int q = t >> 6, j = t & 63;
    const float* zp = g_zpart + ((size_t)(b * 4096 + c * 64) * 64);
    float s = 0.f;
    #pragma unroll 4
    for (int k = q * 16; k < q * 16 + 16; k++) s += zp[k * 64 + j];
    __shared__ float red[256];
    red[t] = s;
    __syncthreads();
    if (t < 64)
        g_zp2[(b * 64 + c) * 64 + t] =
            red[t] + red[t + 64] + red[t + 128] + red[t + 192];
}

__global__ __launch_bounds__(64) void zred2_kernel(float* __restrict__ out)
{
    int b = blockIdx.x;
    int j = threadIdx.x;
    float s = 0.f;
    #pragma unroll 8
    for (int c = 0; c < 64; c++) s += g_zp2[(b * 64 + c) * 64 + j];
    out[131072 + b * 64 + j] = s * (1.f / 61440.f);
}

// ---------------- launch ---------------------------------------------------
extern "C" void kernel_launch(void* const* d_in, const int* in_sizes, int n_in,
                              void* d_out, int out_size)
{
    const float* x   = (const float*)d_in[0];
    const float* z   = (const float*)d_in[1];
    const float* Wm2 = (const float*)d_in[2];
    const float* bm2 = (const float*)d_in[3];
    const float* Wm3 = (const float*)d_in[4];
    const float* bm3 = (const float*)d_in[5];
    const float* Wv2 = (const float*)d_in[6];
    const float* bv2 = (const float*)d_in[7];
    const float* Wv3 = (const float*)d_in[8];
    const float* bv3 = (const float*)d_in[9];
    const float* Wmx = (const float*)d_in[10];
    const float* bmx = (const float*)d_in[11];
    const float* Wvx = (const float*)d_in[12];
    const float* bvx = (const float*)d_in[13];
    const float* Wmz = (const float*)d_in[14];
    const float* bmz = (const float*)d_in[15];
    const float* Wvz = (const float*)d_in[16];
    const float* bvz = (const float*)d_in[17];
    float* out = (float*)d_out;

    cudaFuncSetAttribute(knn_kernel,
                         cudaFuncAttributeMaxDynamicSharedMemorySize, KNN_SMEM);

    zmix_kernel<<<1, 288>>>(z, Wmz, bmz, Wvz, bvz);
    knn_kernel<<<KNN_BLOCKS, 1024, KNN_SMEM>>>(x);
    feat_kernel<<<16384, 128>>>(x,
                                Wm2, bm2, Wm3, bm3, Wv2, bv2, Wv3, bv3,
                                Wmx, bmx, Wvx, bvx, out);
    zred1_kernel<<<256, 256>>>();
    zred2_kernel<<<4, 64>>>(out);
}

// round 13
// speedup vs baseline: 2.1169x; 1.0625x over previous
#include <cuda_runtime.h>
#include <cuda_bf16.h>
#include <math.h>
#include <float.h>

// Shapes (fixed): B=4, NP=4096, D_FEAT=8, N=16, DM=16, DO=8, NM=64, PNM=64
#define BIGF 99999999.0f

// ---------------- scratch (__device__ globals) ----------------------------
__device__ int   g_idx[4 * 4096 * 16];      // knn indices, ascending-distance order
__device__ float g_zpart[4 * 4096 * 64];    // per-(b,n) z partial sums
__device__ float g_zp2[4 * 64 * 64];        // stage-1 z reduction partials
__device__ float g_zm[4 * 8];               // z @ Wmz + bmz
__device__ float g_zv[4 * 64];              // z @ Wvz + bvz

// ---------------- z-mixing biases -----------------------------------------
__global__ void zmix_kernel(const float* __restrict__ z,
                            const float* __restrict__ Wmz, const float* __restrict__ bmz,
                            const float* __restrict__ Wvz, const float* __restrict__ bvz)
{
    int t = threadIdx.x;
    if (t < 256) {                        // zv: 4 batches x 64
        int b = t >> 6, j = t & 63;
        float s = bvz[j];
        #pragma unroll 8
        for (int p = 0; p < 64; p++) s = fmaf(z[b * 64 + p], Wvz[p * 64 + j], s);
        g_zv[t] = s;
    } else if (t < 288) {                 // zm: 4 batches x 8
        int q = t - 256;
        int b = q >> 3, j = q & 7;
        float s = bmz[j];
        #pragma unroll 8
        for (int p = 0; p < 64; p++) s = fmaf(z[b * 64 + p], Wmz[p * 8 + j], s);
        g_zm[q] = s;
    }
}

#define CE(a, b) { float _mn = fminf(a, b); b = fmaxf(a, b); a = _mn; }

// ---------------- kNN: persistent, warp-per-query, batched bitonic --------
// Key substitution: for fixed query i, ascending d2 == ascending
// e = n2j/2 - dot(i,j)  (e = (d2 - n2i)/2, query-constant offset/scale).
// n2 stored halved (h = 0.5*n2; lossless, exact path recovers n2 = 2h
// bitwise). e computed by seeding the FMA chain with h_j and using negated
// query operands (free FFMA modifiers) -> no FADD, no -2x op, no predicates
// (negative keys order correctly as floats; the self-candidate is the
// deterministic global-min key and is mapped to BIG in the exact stage).
// key = (e_bits & ~0xFFF) | j; per-lane top-8 via batched bitonic merge
// (sort4 + 4-min partial merge + 12-CE clean = exact top-8 of union);
// 20-round tournament (16 + 1 self + 3 quantization margin); survivors ->
// reference-exact recompute + (dist, idx) rank sort.
#define KNN_SMEM (4096*16*2 + 4096*4)   // xs0, xs1, n2h = 147456 B
#define KNN_BLOCKS 148

__global__ __launch_bounds__(1024, 1) void knn_kernel(const float* __restrict__ x)
{
    extern __shared__ char smem_raw[];
    float4* xs0 = (float4*)smem_raw;                        // [4096]
    float4* xs1 = (float4*)(smem_raw + 4096 * 16);          // [4096]
    float*  n2h = (float*) (smem_raw + 4096 * 32);          // [4096] = n2/2

    int b = blockIdx.x & 3;
    int r = blockIdx.x >> 2;               // 0..36
    // contiguous query range: 4096 = 37*110 + 26 -> first 26 ranges get 111
    int qbase = r * 110 + (r < 26 ? r : 26);
    int qcnt  = 110 + (r < 26 ? 1 : 0);

    int tid  = threadIdx.x;
    int w    = tid >> 5;
    int lane = tid & 31;

    const float* xb = x + (b << 15);

    // stage points + exact n2 (mul + serial rn adds), stored halved
    #pragma unroll
    for (int k = 0; k < 4; k++) {
        int p = tid + (k << 10);
        float4 a = *(const float4*)(xb + p * 8);
        float4 c = *(const float4*)(xb + p * 8 + 4);
        xs0[p] = a;
        xs1[p] = c;
        float s = __fmul_rn(a.x, a.x);
        s = __fadd_rn(s, __fmul_rn(a.y, a.y));
        s = __fadd_rn(s, __fmul_rn(a.z, a.z));
        s = __fadd_rn(s, __fmul_rn(a.w, a.w));
        s = __fadd_rn(s, __fmul_rn(c.x, c.x));
        s = __fadd_rn(s, __fmul_rn(c.y, c.y));
        s = __fadd_rn(s, __fmul_rn(c.z, c.z));
        s = __fadd_rn(s, __fmul_rn(c.w, c.w));
        n2h[p] = 0.5f * s;                 // lossless halving
    }
    __syncthreads();

    // warp-level query loop (guard is warp-uniform; shuffles stay full-mask)
    for (int q = w; q < qcnt; q += 32) {
        int i = qbase + q;
        float4 a0 = xs0[i];
        float4 a1 = xs1[i];

        // ---- single pass: per-lane top-8 of e-keys, batched bitonic ----
        float s0 = FLT_MAX, s1 = FLT_MAX, s2 = FLT_MAX, s3 = FLT_MAX,
              s4 = FLT_MAX, s5 = FLT_MAX, s6 = FLT_MAX, s7 = FLT_MAX;
        {
            int j = lane;
            #pragma unroll 1
            for (int kb = 0; kb < 32; kb++) {
                float bk[4];
                #pragma unroll
                for (int c4 = 0; c4 < 4; c4++) {
                    int jj = j + (c4 << 5);
                    float4 p0 = xs0[jj];
                    float4 p1 = xs1[jj];
                    // e = h_j - dot : seed chain with h_j, negated query ops
                    float acc = n2h[jj];
                    acc = fmaf(-a0.x, p0.x, acc);
                    acc = fmaf(-a0.y, p0.y, acc);
                    acc = fmaf(-a0.z, p0.z, acc);
                    acc = fmaf(-a0.w, p0.w, acc);
                    acc = fmaf(-a1.x, p1.x, acc);
                    acc = fmaf(-a1.y, p1.y, acc);
                    acc = fmaf(-a1.z, p1.z, acc);
                    acc = fmaf(-a1.w, p1.w, acc);
                    unsigned kbits = (__float_as_uint(acc) & 0xFFFFF000u) | (unsigned)jj;
                    bk[c4] = __uint_as_float(kbits);
                }
                // sort4 (ascending)
                CE(bk[0], bk[1]); CE(bk[2], bk[3]);
                CE(bk[0], bk[2]); CE(bk[1], bk[3]);
                CE(bk[1], bk[2]);
                // partial bitonic merge: keep min-half (exact top-8 of union)
                s4 = fminf(s4, bk[3]);
                s5 = fminf(s5, bk[2]);
                s6 = fminf(s6, bk[1]);
                s7 = fminf(s7, bk[0]);
                // bitonic clean of 8 (result sorted ascending)
                CE(s0, s4); CE(s1, s5); CE(s2, s6); CE(s3, s7);
                CE(s0, s2); CE(s1, s3); CE(s4, s6); CE(s5, s7);
                CE(s0, s1); CE(s2, s3); CE(s4, s5); CE(s6, s7);
                j += 128;
            }
        }

        // ---- 20-round tournament: lane r keeps the r-th smallest key ----
        float head = s0;
        float surv = FLT_MAX;
        #pragma unroll 1
        for (int round = 0; round < 20; round++) {
            float m = head;
            m = fminf(m, __shfl_xor_sync(0xffffffffu, m, 16));
            m = fminf(m, __shfl_xor_sync(0xffffffffu, m, 8));
            m = fminf(m, __shfl_xor_sync(0xffffffffu, m, 4));
            m = fminf(m, __shfl_xor_sync(0xffffffffu, m, 2));
            m = fminf(m, __shfl_xor_sync(0xffffffffu, m, 1));
            if (round == lane) surv = m;
            unsigned bal = __ballot_sync(0xffffffffu, head == m);
            int leader = __ffs(bal) - 1;
            if (lane == leader) {
                s0 = s1; s1 = s2; s2 = s3; s3 = s4;
                s4 = s5; s5 = s6; s6 = s7; s7 = FLT_MAX;
                head = s0;
            }
        }

        // ---- exact recompute + (dist, idx) rank sort of the survivors ----
        {
            bool valid = (lane < 20) && (surv != FLT_MAX);
            int j = (int)(__float_as_uint(surv) & 0xFFFu);
            unsigned long long pk = 0xffffffffffffffffull;
            if (valid) {
                float4 p0 = xs0[j];
                float4 p1 = xs1[j];
                // reference-exact: serial FMA dot, (n2i+n2j)-2*dot, sqrt
                float n2i = 2.0f * n2h[i];     // lossless
                float n2j = 2.0f * n2h[j];
                float dot = __fmul_rn(a0.x, p0.x);
                dot = __fmaf_rn(a0.y, p0.y, dot);
                dot = __fmaf_rn(a0.z, p0.z, dot);
                dot = __fmaf_rn(a0.w, p0.w, dot);
                dot = __fmaf_rn(a1.x, p1.x, dot);
                dot = __fmaf_rn(a1.y, p1.y, dot);
                dot = __fmaf_rn(a1.z, p1.z, dot);
                dot = __fmaf_rn(a1.w, p1.w, dot);
                float d2 = __fsub_rn(__fadd_rn(n2i, n2j), __fmul_rn(2.0f, dot));
                float dd = sqrtf(fmaxf(d2, 0.0f));
                if (dd == 0.0f || j == i) dd = BIGF;
                pk = ((unsigned long long)__float_as_uint(dd) << 32) | (unsigned)j;
            }
            int rank = 0;
            #pragma unroll
            for (int m = 0; m < 32; m++) {
                unsigned long long o = __shfl_sync(0xffffffffu, pk, m);
                rank += (o < pk) ? 1 : 0;
            }
            if (valid && rank < 16)
                g_idx[(b * 4096 + i) * 16 + rank] = j;
        }
    }
}

// ---------------- features + fused matmuls: block per (b,n) ---------------
// (EXACT R6 version — known-good 76us; pinned.)
// DM=16, K = 2*DM = 32 moment columns (cols 0..15 order-2, 16..31 order-3).
__global__ __launch_bounds__(128) void feat_kernel(
    const float* __restrict__ x,
    const float* __restrict__ Wm2, const float* __restrict__ bm2,
    const float* __restrict__ Wm3, const float* __restrict__ bm3,
    const float* __restrict__ Wv2, const float* __restrict__ bv2,
    const float* __restrict__ Wv3, const float* __restrict__ bv3,
    const float* __restrict__ Wmx, const float* __restrict__ bmx,
    const float* __restrict__ Wvx, const float* __restrict__ bvx,
    float* __restrict__ xout)
{
    int b = blockIdx.x >> 12;
    int n = blockIdx.x & 4095;
    int t = threadIdx.x;

    __shared__ __align__(16) float g[16][8];
    __shared__ __align__(16) float msm[15][32];
    __shared__ __align__(16) float vsm[15][32];
    __shared__ float mpart[8][8][15];   // [j][slice][r]
    __shared__ float xr[8][15];

    // gather 16 neighbor feature vectors
    {
        int s = t >> 3, d = t & 7;
        int nb = g_idx[(b * 4096 + n) * 16 + s] & 4095;
        g[s][d] = x[(size_t)(b * 4096 + nb) * 8 + d];
    }

    // feature-phase role
    int c   = t & 31;
    int mat = (t >> 5) & 1;
    int rh  = t >> 6;
    bool o3 = (c >= 16);
    int  k  = o3 ? (c - 16) : c;
    float w0, w1, w2 = 0.f, bb;
    if (!o3) {
        w0 = mat ? Wv2[k]      : Wm2[k];
        w1 = mat ? Wv2[16 + k] : Wm2[16 + k];
        bb = mat ? bv2[k]      : bm2[k];
    } else {
        w0 = mat ? Wv3[k]      : Wm3[k];
        w1 = mat ? Wv3[16 + k] : Wm3[16 + k];
        w2 = mat ? Wv3[32 + k] : Wm3[32 + k];
        bb = mat ? bv3[k]      : bm3[k];
    }
    __syncthreads();

    // r-invariant base: order2 p = g0*w0+b ; order3 p = g0*w0+g1*w1+b
    float p[8];
    #pragma unroll
    for (int d = 0; d < 8; d++) {
        float base = fmaf(g[0][d], w0, bb);
        p[d] = o3 ? fmaf(g[1][d], w1, base) : base;
    }
    float wlast = o3 ? w2 : w1;
    float* smo = mat ? &vsm[0][0] : &msm[0][0];

    int r0 = rh ? 8 : 0;
    int r1 = rh ? 15 : 8;
    for (int r = r0; r < r1; r++) {
        float ssum = 0.f;
        if (o3 && r == 14) {
            // tuple (0,2,3): g0*w0 + g2*w1 + g3*w2 + b
            #pragma unroll
            for (int d = 0; d < 8; d++) {
                float v = fmaf(g[3][d], w2,
                          fmaf(g[2][d], w1,
                          fmaf(g[0][d], w0, bb)));
                ssum += fmaxf(v, 0.f);
            }
        } else {
            int a = o3 ? (r + 2) : (r + 1);
            #pragma unroll
            for (int d = 0; d < 8; d++)
                ssum += fmaxf(fmaf(g[a][d], wlast, p[d]), 0.f);
        }
        smo[r * 32 + c] = ssum * 0.125f;   // mean over d (8)
    }
    __syncthreads();

    if (t < 64) {
        // v-matmul: output j=t, K=32, 15 tuples
        float acc[15];
        #pragma unroll
        for (int r = 0; r < 15; r++) acc[r] = 0.f;
        #pragma unroll
        for (int k4 = 0; k4 < 32; k4 += 4) {
            float q0 = Wvx[(k4 + 0) * 64 + t];
            float q1 = Wvx[(k4 + 1) * 64 + t];
            float q2 = Wvx[(k4 + 2) * 64 + t];
            float q3 = Wvx[(k4 + 3) * 64 + t];
            #pragma unroll
            for (int r = 0; r < 15; r++) {
                float4 vv = *(const float4*)&vsm[r][k4];
                acc[r] = fmaf(vv.x, q0, acc[r]);
                acc[r] = fmaf(vv.y, q1, acc[r]);
                acc[r] = fmaf(vv.z, q2, acc[r]);
                acc[r] = fmaf(vv.w, q3, acc[r]);
            }
        }
        float bias = bvx[t] + g_zv[b * 64 + t];
        float s = 0.f;
        #pragma unroll
        for (int r = 0; r < 15; r++) s += fmaxf(acc[r] + bias, 0.f);
        g_zpart[(size_t)(b * 4096 + n) * 64 + t] = s;
    } else {
        // m-matmul: 8 outputs x 8 k-slices of 4
        int q = t - 64;
        int j = q >> 3;
        int sl = q & 7;
        int k0 = sl * 4;
        float q0 = Wmx[(k0 + 0) * 8 + j];
        float q1 = Wmx[(k0 + 1) * 8 + j];
        float q2 = Wmx[(k0 + 2) * 8 + j];
        float q3 = Wmx[(k0 + 3) * 8 + j];
        #pragma unroll
        for (int r = 0; r < 15; r++) {
            float4 mv = *(const float4*)&msm[r][k0];
            float a = mv.x * q0;
            a = fmaf(mv.y, q1, a);
            a = fmaf(mv.z, q2, a);
            a = fmaf(mv.w, q3, a);
            mpart[j][sl][r] = a;
        }
    }
    __syncthreads();

    if (t < 120) {
        int j = t / 15, r = t % 15;
        float s = 0.f;
        #pragma unroll
        for (int sl = 0; sl < 8; sl++) s += mpart[j][sl][r];
        xr[j][r] = fmaxf(s + bmx[j] + g_zm[b * 8 + j], 0.f);
    }
    __syncthreads();
    if (t < 8) {
        float s = 0.f;
        #pragma unroll
        for (int r = 0; r < 15; r++) s += xr[t][r];
        xout[(size_t)b * 32768 + n * 8 + t] = s * (1.f / 15.f);
    }
}

// ---------------- z reduction, two-stage ----------------------------------
__global__ __launch_bounds__(256) void zred1_kernel()
{
    int b = blockIdx.x >> 6;
    int c = blockIdx.x & 63;
    int t = threadIdx.x;
    int q = t >> 6, j = t & 63;
    const float* zp = g_zpart + ((size_t)(b * 4096 + c * 64) * 64);
    float s = 0.f;
    #pragma unroll 16
    for (int k = q * 16; k < q * 16 + 16; k++) s += zp[k * 64 + j];
    __shared__ float red[256];
    red[t] = s;
    __syncthreads();
    if (t < 64)
        g_zp2[(b * 64 + c) * 64 + t] =
            red[t] + red[t + 64] + red[t + 128] + red[t + 192];
}

__global__ __launch_bounds__(64) void zred2_kernel(float* __restrict__ out)
{
    int b = blockIdx.x;
    int j = threadIdx.x;
    float s = 0.f;
    #pragma unroll 8
    for (int c = 0; c < 64; c++) s += g_zp2[(b * 64 + c) * 64 + j];
    out[131072 + b * 64 + j] = s * (1.f / 61440.f);
}

// ---------------- launch ---------------------------------------------------
extern "C" void kernel_launch(void* const* d_in, const int* in_sizes, int n_in,
                              void* d_out, int out_size)
{
    const float* x   = (const float*)d_in[0];
    const float* z   = (const float*)d_in[1];
    const float* Wm2 = (const float*)d_in[2];
    const float* bm2 = (const float*)d_in[3];
    const float* Wm3 = (const float*)d_in[4];
    const float* bm3 = (const float*)d_in[5];
    const float* Wv2 = (const float*)d_in[6];
    const float* bv2 = (const float*)d_in[7];
    const float* Wv3 = (const float*)d_in[8];
    const float* bv3 = (const float*)d_in[9];
    const float* Wmx = (const float*)d_in[10];
    const float* bmx = (const float*)d_in[11];
    const float* Wvx = (const float*)d_in[12];
    const float* bvx = (const float*)d_in[13];
    const float* Wmz = (const float*)d_in[14];
    const float* bmz = (const float*)d_in[15];
    const float* Wvz = (const float*)d_in[16];
    const float* bvz = (const float*)d_in[17];
    float* out = (float*)d_out;

    cudaFuncSetAttribute(knn_kernel,
                         cudaFuncAttributeMaxDynamicSharedMemorySize, KNN_SMEM);

    zmix_kernel<<<1, 288>>>(z, Wmz, bmz, Wvz, bvz);
    knn_kernel<<<KNN_BLOCKS, 1024, KNN_SMEM>>>(x);
    feat_kernel<<<16384, 128>>>(x,
                                Wm2, bm2, Wm3, bm3, Wv2, bv2, Wv3, bv3,
                                Wmx, bmx, Wvx, bvx, out);
    zred1_kernel<<<256, 256>>>();
    zred2_kernel<<<4, 64>>>(out);
}

// round 14
// speedup vs baseline: 2.3196x; 1.0958x over previous
#include <cuda_runtime.h>
#include <cuda_bf16.h>
#include <math.h>
#include <float.h>

// Shapes (fixed): B=4, NP=4096, D_FEAT=8, N=16, DM=16, DO=8, NM=64, PNM=64
#define BIGF 99999999.0f

// ---------------- scratch (__device__ globals) ----------------------------
__device__ int   g_idx[4 * 4096 * 16];      // knn indices, ascending-distance order
__device__ float g_zpart[4 * 4096 * 64];    // per-(b,n) z partial sums
__device__ float g_zp2[4 * 64 * 64];        // stage-1 z reduction partials
__device__ float g_zm[4 * 8];               // z @ Wmz + bmz
__device__ float g_zv[4 * 64];              // z @ Wvz + bvz

// ---------------- z-mixing biases -----------------------------------------
__global__ void zmix_kernel(const float* __restrict__ z,
                            const float* __restrict__ Wmz, const float* __restrict__ bmz,
                            const float* __restrict__ Wvz, const float* __restrict__ bvz)
{
    int t = threadIdx.x;
    if (t < 256) {                        // zv: 4 batches x 64
        int b = t >> 6, j = t & 63;
        float s = bvz[j];
        #pragma unroll 8
        for (int p = 0; p < 64; p++) s = fmaf(z[b * 64 + p], Wvz[p * 64 + j], s);
        g_zv[t] = s;
    } else if (t < 288) {                 // zm: 4 batches x 8
        int q = t - 256;
        int b = q >> 3, j = q & 7;
        float s = bmz[j];
        #pragma unroll 8
        for (int p = 0; p < 64; p++) s = fmaf(z[b * 64 + p], Wmz[p * 8 + j], s);
        g_zm[q] = s;
    }
}

#define CE(a, b) { float _mn = fminf(a, b); b = fmaxf(a, b); a = _mn; }

// ---------------- kNN: persistent, 2 queries/warp, batched bitonic --------
// smem-crossbar-bound -> each candidate load (2xLDS.128 + LDS.32 = 36B) now
// feeds TWO queries' e-key chains (18B/pair). Per-query math is identical
// to R13: e = h_j - dot (h = n2/2, lossless), negated-operand FFMA chain,
// key = (e_bits & ~0xFFF) | j, batched bitonic top-8 (sort4 + 4-min merge +
// 12-CE clean), 20-round tournament, reference-exact recompute + (dist,idx)
// rank sort -> output bit-identical. Odd query-count tail: iB = iA
// (duplicate, same writes, deterministic).
#define KNN_SMEM (4096*16*2 + 4096*4)   // xs0, xs1, n2h = 147456 B
#define KNN_BLOCKS 148

__global__ __launch_bounds__(1024, 1) void knn_kernel(const float* __restrict__ x)
{
    extern __shared__ char smem_raw[];
    float4* xs0 = (float4*)smem_raw;                        // [4096]
    float4* xs1 = (float4*)(smem_raw + 4096 * 16);          // [4096]
    float*  n2h = (float*) (smem_raw + 4096 * 32);          // [4096] = n2/2

    int b = blockIdx.x & 3;
    int r = blockIdx.x >> 2;               // 0..36
    // contiguous query range: 4096 = 37*110 + 26 -> first 26 ranges get 111
    int qbase = r * 110 + (r < 26 ? r : 26);
    int qcnt  = 110 + (r < 26 ? 1 : 0);
    int npair = (qcnt + 1) >> 1;

    int tid  = threadIdx.x;
    int w    = tid >> 5;
    int lane = tid & 31;

    const float* xb = x + (b << 15);

    // stage points + exact n2 (mul + serial rn adds), stored halved
    #pragma unroll
    for (int k = 0; k < 4; k++) {
        int p = tid + (k << 10);
        float4 a = *(const float4*)(xb + p * 8);
        float4 c = *(const float4*)(xb + p * 8 + 4);
        xs0[p] = a;
        xs1[p] = c;
        float s = __fmul_rn(a.x, a.x);
        s = __fadd_rn(s, __fmul_rn(a.y, a.y));
        s = __fadd_rn(s, __fmul_rn(a.z, a.z));
        s = __fadd_rn(s, __fmul_rn(a.w, a.w));
        s = __fadd_rn(s, __fmul_rn(c.x, c.x));
        s = __fadd_rn(s, __fmul_rn(c.y, c.y));
        s = __fadd_rn(s, __fmul_rn(c.z, c.z));
        s = __fadd_rn(s, __fmul_rn(c.w, c.w));
        n2h[p] = 0.5f * s;                 // lossless halving
    }
    __syncthreads();

    // warp-level query-pair loop (guard warp-uniform; shuffles full-mask)
    for (int qp = w; qp < npair; qp += 32) {
        int iA = qbase + 2 * qp;
        int iB = (2 * qp + 1 < qcnt) ? (iA + 1) : iA;
        float4 aA0 = xs0[iA], aA1 = xs1[iA];
        float4 aB0 = xs0[iB], aB1 = xs1[iB];

        // ---- single pass: per-lane top-8 of e-keys for both queries ----
        float A0 = FLT_MAX, A1 = FLT_MAX, A2 = FLT_MAX, A3 = FLT_MAX,
              A4 = FLT_MAX, A5 = FLT_MAX, A6 = FLT_MAX, A7 = FLT_MAX;
        float B0 = FLT_MAX, B1 = FLT_MAX, B2 = FLT_MAX, B3 = FLT_MAX,
              B4 = FLT_MAX, B5 = FLT_MAX, B6 = FLT_MAX, B7 = FLT_MAX;
        {
            int j = lane;
            #pragma unroll 1
            for (int kb = 0; kb < 32; kb++) {
                float bkA[4], bkB[4];
                #pragma unroll
                for (int c4 = 0; c4 < 4; c4++) {
                    int jj = j + (c4 << 5);
                    float4 p0 = xs0[jj];
                    float4 p1 = xs1[jj];
                    float h  = n2h[jj];
                    float eA = h;
                    eA = fmaf(-aA0.x, p0.x, eA);
                    eA = fmaf(-aA0.y, p0.y, eA);
                    eA = fmaf(-aA0.z, p0.z, eA);
                    eA = fmaf(-aA0.w, p0.w, eA);
                    eA = fmaf(-aA1.x, p1.x, eA);
                    eA = fmaf(-aA1.y, p1.y, eA);
                    eA = fmaf(-aA1.z, p1.z, eA);
                    eA = fmaf(-aA1.w, p1.w, eA);
                    bkA[c4] = __uint_as_float(
                        (__float_as_uint(eA) & 0xFFFFF000u) | (unsigned)jj);
                    float eB = h;
                    eB = fmaf(-aB0.x, p0.x, eB);
                    eB = fmaf(-aB0.y, p0.y, eB);
                    eB = fmaf(-aB0.z, p0.z, eB);
                    eB = fmaf(-aB0.w, p0.w, eB);
                    eB = fmaf(-aB1.x, p1.x, eB);
                    eB = fmaf(-aB1.y, p1.y, eB);
                    eB = fmaf(-aB1.z, p1.z, eB);
                    eB = fmaf(-aB1.w, p1.w, eB);
                    bkB[c4] = __uint_as_float(
                        (__float_as_uint(eB) & 0xFFFFF000u) | (unsigned)jj);
                }
                // query A: sort4 + partial merge + clean
                CE(bkA[0], bkA[1]); CE(bkA[2], bkA[3]);
                CE(bkA[0], bkA[2]); CE(bkA[1], bkA[3]);
                CE(bkA[1], bkA[2]);
                A4 = fminf(A4, bkA[3]);
                A5 = fminf(A5, bkA[2]);
                A6 = fminf(A6, bkA[1]);
                A7 = fminf(A7, bkA[0]);
                CE(A0, A4); CE(A1, A5); CE(A2, A6); CE(A3, A7);
                CE(A0, A2); CE(A1, A3); CE(A4, A6); CE(A5, A7);
                CE(A0, A1); CE(A2, A3); CE(A4, A5); CE(A6, A7);
                // query B: sort4 + partial merge + clean
                CE(bkB[0], bkB[1]); CE(bkB[2], bkB[3]);
                CE(bkB[0], bkB[2]); CE(bkB[1], bkB[3]);
                CE(bkB[1], bkB[2]);
                B4 = fminf(B4, bkB[3]);
                B5 = fminf(B5, bkB[2]);
                B6 = fminf(B6, bkB[1]);
                B7 = fminf(B7, bkB[0]);
                CE(B0, B4); CE(B1, B5); CE(B2, B6); CE(B3, B7);
                CE(B0, B2); CE(B1, B3); CE(B4, B6); CE(B5, B7);
                CE(B0, B1); CE(B2, B3); CE(B4, B5); CE(B6, B7);
                j += 128;
            }
        }

        // ---- per query: 20-round tournament + exact re-rank ----
        #pragma unroll 1
        for (int qq = 0; qq < 2; qq++) {
            int i = qq ? iB : iA;
            float s0 = qq ? B0 : A0, s1 = qq ? B1 : A1,
                  s2 = qq ? B2 : A2, s3 = qq ? B3 : A3,
                  s4 = qq ? B4 : A4, s5 = qq ? B5 : A5,
                  s6 = qq ? B6 : A6, s7 = qq ? B7 : A7;

            float head = s0;
            float surv = FLT_MAX;
            #pragma unroll 1
            for (int round = 0; round < 20; round++) {
                float m = head;
                m = fminf(m, __shfl_xor_sync(0xffffffffu, m, 16));
                m = fminf(m, __shfl_xor_sync(0xffffffffu, m, 8));
                m = fminf(m, __shfl_xor_sync(0xffffffffu, m, 4));
                m = fminf(m, __shfl_xor_sync(0xffffffffu, m, 2));
                m = fminf(m, __shfl_xor_sync(0xffffffffu, m, 1));
                if (round == lane) surv = m;
                unsigned bal = __ballot_sync(0xffffffffu, head == m);
                int leader = __ffs(bal) - 1;
                if (lane == leader) {
                    s0 = s1; s1 = s2; s2 = s3; s3 = s4;
                    s4 = s5; s5 = s6; s6 = s7; s7 = FLT_MAX;
                    head = s0;
                }
            }

            bool valid = (lane < 20) && (surv != FLT_MAX);
            int j = (int)(__float_as_uint(surv) & 0xFFFu);
            unsigned long long pk = 0xffffffffffffffffull;
            if (valid) {
                float4 a0 = xs0[i], a1 = xs1[i];
                float4 p0 = xs0[j], p1 = xs1[j];
                // reference-exact: serial FMA dot, (n2i+n2j)-2*dot, sqrt
                float n2i = 2.0f * n2h[i];     // lossless
                float n2j = 2.0f * n2h[j];
                float dot = __fmul_rn(a0.x, p0.x);
                dot = __fmaf_rn(a0.y, p0.y, dot);
                dot = __fmaf_rn(a0.z, p0.z, dot);
                dot = __fmaf_rn(a0.w, p0.w, dot);
                dot = __fmaf_rn(a1.x, p1.x, dot);
                dot = __fmaf_rn(a1.y, p1.y, dot);
                dot = __fmaf_rn(a1.z, p1.z, dot);
                dot = __fmaf_rn(a1.w, p1.w, dot);
                float d2 = __fsub_rn(__fadd_rn(n2i, n2j), __fmul_rn(2.0f, dot));
                float dd = sqrtf(fmaxf(d2, 0.0f));
                if (dd == 0.0f || j == i) dd = BIGF;
                pk = ((unsigned long long)__float_as_uint(dd) << 32) | (unsigned)j;
            }
            int rank = 0;
            #pragma unroll
            for (int m = 0; m < 32; m++) {
                unsigned long long o = __shfl_sync(0xffffffffu, pk, m);
                rank += (o < pk) ? 1 : 0;
            }
            if (valid && rank < 16)
                g_idx[(b * 4096 + i) * 16 + rank] = j;
        }
    }
}

// ---------------- features + fused matmuls: block per (b,n) ---------------
// (EXACT R6 version — known-good 76us; pinned.)
// DM=16, K = 2*DM = 32 moment columns (cols 0..15 order-2, 16..31 order-3).
__global__ __launch_bounds__(128) void feat_kernel(
    const float* __restrict__ x,
    const float* __restrict__ Wm2, const float* __restrict__ bm2,
    const float* __restrict__ Wm3, const float* __restrict__ bm3,
    const float* __restrict__ Wv2, const float* __restrict__ bv2,
    const float* __restrict__ Wv3, const float* __restrict__ bv3,
    const float* __restrict__ Wmx, const float* __restrict__ bmx,
    const float* __restrict__ Wvx, const float* __restrict__ bvx,
    float* __restrict__ xout)
{
    int b = blockIdx.x >> 12;
    int n = blockIdx.x & 4095;
    int t = threadIdx.x;

    __shared__ __align__(16) float g[16][8];
    __shared__ __align__(16) float msm[15][32];
    __shared__ __align__(16) float vsm[15][32];
    __shared__ float mpart[8][8][15];   // [j][slice][r]
    __shared__ float xr[8][15];

    // gather 16 neighbor feature vectors
    {
        int s = t >> 3, d = t & 7;
        int nb = g_idx[(b * 4096 + n) * 16 + s] & 4095;
        g[s][d] = x[(size_t)(b * 4096 + nb) * 8 + d];
    }

    // feature-phase role
    int c   = t & 31;
    int mat = (t >> 5) & 1;
    int rh  = t >> 6;
    bool o3 = (c >= 16);
    int  k  = o3 ? (c - 16) : c;
    float w0, w1, w2 = 0.f, bb;
    if (!o3) {
        w0 = mat ? Wv2[k]      : Wm2[k];
        w1 = mat ? Wv2[16 + k] : Wm2[16 + k];
        bb = mat ? bv2[k]      : bm2[k];
    } else {
        w0 = mat ? Wv3[k]      : Wm3[k];
        w1 = mat ? Wv3[16 + k] : Wm3[16 + k];
        w2 = mat ? Wv3[32 + k] : Wm3[32 + k];
        bb = mat ? bv3[k]      : bm3[k];
    }
    __syncthreads();

    // r-invariant base: order2 p = g0*w0+b ; order3 p = g0*w0+g1*w1+b
    float p[8];
    #pragma unroll
    for (int d = 0; d < 8; d++) {
        float base = fmaf(g[0][d], w0, bb);
        p[d] = o3 ? fmaf(g[1][d], w1, base) : base;
    }
    float wlast = o3 ? w2 : w1;
    float* smo = mat ? &vsm[0][0] : &msm[0][0];

    int r0 = rh ? 8 : 0;
    int r1 = rh ? 15 : 8;
    for (int r = r0; r < r1; r++) {
        float ssum = 0.f;
        if (o3 && r == 14) {
            // tuple (0,2,3): g0*w0 + g2*w1 + g3*w2 + b
            #pragma unroll
            for (int d = 0; d < 8; d++) {
                float v = fmaf(g[3][d], w2,
                          fmaf(g[2][d], w1,
                          fmaf(g[0][d], w0, bb)));
                ssum += fmaxf(v, 0.f);
            }
        } else {
            int a = o3 ? (r + 2) : (r + 1);
            #pragma unroll
            for (int d = 0; d < 8; d++)
                ssum += fmaxf(fmaf(g[a][d], wlast, p[d]), 0.f);
        }
        smo[r * 32 + c] = ssum * 0.125f;   // mean over d (8)
    }
    __syncthreads();

    if (t < 64) {
        // v-matmul: output j=t, K=32, 15 tuples
        float acc[15];
        #pragma unroll
        for (int r = 0; r < 15; r++) acc[r] = 0.f;
        #pragma unroll
        for (int k4 = 0; k4 < 32; k4 += 4) {
            float q0 = Wvx[(k4 + 0) * 64 + t];
            float q1 = Wvx[(k4 + 1) * 64 + t];
            float q2 = Wvx[(k4 + 2) * 64 + t];
            float q3 = Wvx[(k4 + 3) * 64 + t];
            #pragma unroll
            for (int r = 0; r < 15; r++) {
                float4 vv = *(const float4*)&vsm[r][k4];
                acc[r] = fmaf(vv.x, q0, acc[r]);
                acc[r] = fmaf(vv.y, q1, acc[r]);
                acc[r] = fmaf(vv.z, q2, acc[r]);
                acc[r] = fmaf(vv.w, q3, acc[r]);
            }
        }
        float bias = bvx[t] + g_zv[b * 64 + t];
        float s = 0.f;
        #pragma unroll
        for (int r = 0; r < 15; r++) s += fmaxf(acc[r] + bias, 0.f);
        g_zpart[(size_t)(b * 4096 + n) * 64 + t] = s;
    } else {
        // m-matmul: 8 outputs x 8 k-slices of 4
        int q = t - 64;
        int j = q >> 3;
        int sl = q & 7;
        int k0 = sl * 4;
        float q0 = Wmx[(k0 + 0) * 8 + j];
        float q1 = Wmx[(k0 + 1) * 8 + j];
        float q2 = Wmx[(k0 + 2) * 8 + j];
        float q3 = Wmx[(k0 + 3) * 8 + j];
        #pragma unroll
        for (int r = 0; r < 15; r++) {
            float4 mv = *(const float4*)&msm[r][k0];
            float a = mv.x * q0;
            a = fmaf(mv.y, q1, a);
            a = fmaf(mv.z, q2, a);
            a = fmaf(mv.w, q3, a);
            mpart[j][sl][r] = a;
        }
    }
    __syncthreads();

    if (t < 120) {
        int j = t / 15, r = t % 15;
        float s = 0.f;
        #pragma unroll
        for (int sl = 0; sl < 8; sl++) s += mpart[j][sl][r];
        xr[j][r] = fmaxf(s + bmx[j] + g_zm[b * 8 + j], 0.f);
    }
    __syncthreads();
    if (t < 8) {
        float s = 0.f;
        #pragma unroll
        for (int r = 0; r < 15; r++) s += xr[t][r];
        xout[(size_t)b * 32768 + n * 8 + t] = s * (1.f / 15.f);
    }
}

// ---------------- z reduction, two-stage ----------------------------------
__global__ __launch_bounds__(256) void zred1_kernel()
{
    int b = blockIdx.x >> 6;
    int c = blockIdx.x & 63;
    int t = threadIdx.x;
    int q = t >> 6, j = t & 63;
    const float* zp = g_zpart + ((size_t)(b * 4096 + c * 64) * 64);
    float s = 0.f;
    #pragma unroll 16
    for (int k = q * 16; k < q * 16 + 16; k++) s += zp[k * 64 + j];
    __shared__ float red[256];
    red[t] = s;
    __syncthreads();
    if (t < 64)
        g_zp2[(b * 64 + c) * 64 + t] =
            red[t] + red[t + 64] + red[t + 128] + red[t + 192];
}

__global__ __launch_bounds__(64) void zred2_kernel(float* __restrict__ out)
{
    int b = blockIdx.x;
    int j = threadIdx.x;
    float s = 0.f;
    #pragma unroll 8
    for (int c = 0; c < 64; c++) s += g_zp2[(b * 64 + c) * 64 + j];
    out[131072 + b * 64 + j] = s * (1.f / 61440.f);
}

// ---------------- launch ---------------------------------------------------
extern "C" void kernel_launch(void* const* d_in, const int* in_sizes, int n_in,
                              void* d_out, int out_size)
{
    const float* x   = (const float*)d_in[0];
    const float* z   = (const float*)d_in[1];
    const float* Wm2 = (const float*)d_in[2];
    const float* bm2 = (const float*)d_in[3];
    const float* Wm3 = (const float*)d_in[4];
    const float* bm3 = (const float*)d_in[5];
    const float* Wv2 = (const float*)d_in[6];
    const float* bv2 = (const float*)d_in[7];
    const float* Wv3 = (const float*)d_in[8];
    const float* bv3 = (const float*)d_in[9];
    const float* Wmx = (const float*)d_in[10];
    const float* bmx = (const float*)d_in[11];
    const float* Wvx = (const float*)d_in[12];
    const float* bvx = (const float*)d_in[13];
    const float* Wmz = (const float*)d_in[14];
    const float* bmz = (const float*)d_in[15];
    const float* Wvz = (const float*)d_in[16];
    const float* bvz = (const float*)d_in[17];
    float* out = (float*)d_out;

    cudaFuncSetAttribute(knn_kernel,
                         cudaFuncAttributeMaxDynamicSharedMemorySize, KNN_SMEM);

    zmix_kernel<<<1, 288>>>(z, Wmz, bmz, Wvz, bvz);
    knn_kernel<<<KNN_BLOCKS, 1024, KNN_SMEM>>>(x);
    feat_kernel<<<16384, 128>>>(x,
                                Wm2, bm2, Wm3, bm3, Wv2, bv2, Wv3, bv3,
                                Wmx, bmx, Wvx, bvx, out);
    zred1_kernel<<<256, 256>>>();
    zred2_kernel<<<4, 64>>>(out);
}

// round 15
// speedup vs baseline: 2.3851x; 1.0283x over previous
#include <cuda_runtime.h>
#include <cuda_bf16.h>
#include <math.h>
#include <float.h>

// Shapes (fixed): B=4, NP=4096, D_FEAT=8, N=16, DM=16, DO=8, NM=64, PNM=64
#define BIGF 99999999.0f

// ---------------- scratch (__device__ globals) ----------------------------
__device__ int   g_idx[4 * 4096 * 16];      // knn indices, ascending-distance order
__device__ float g_zpart[4 * 4096 * 64];    // per-(b,n) z partial sums
__device__ float g_zp2[4 * 64 * 64];        // stage-1 z reduction partials
__device__ float g_zm[4 * 8];               // z @ Wmz + bmz
__device__ float g_zv[4 * 64];              // z @ Wvz + bvz

#define CE(a, b) { float _mn = fminf(a, b); b = fmaxf(a, b); a = _mn; }

__device__ __forceinline__ unsigned long long pack2(float a, float b) {
    unsigned long long r;
    asm("mov.b64 %0, {%1, %2};" : "=l"(r) : "f"(a), "f"(b));
    return r;
}
__device__ __forceinline__ void unpack2(unsigned long long v, float& a, float& b) {
    asm("mov.b64 {%0, %1}, %2;" : "=f"(a), "=f"(b) : "l"(v));
}
__device__ __forceinline__ void ffma2(unsigned long long& acc,
                                      unsigned long long ab, unsigned long long cd) {
    asm("fma.rn.f32x2 %0, %1, %2, %0;" : "+l"(acc) : "l"(ab), "l"(cd));
}

// ---------------- kNN: persistent, 2 queries/warp, batched bitonic --------
// (R14 selection path — bit-identical output; do not touch.)
// Blocks with r==36 (one per batch, least-loaded: 110 queries) additionally
// compute the zmix biases for their batch before the query loop (arithmetic
// order identical to the old zmix kernel; knn completes before feat runs).
#define KNN_SMEM (4096*16*2 + 4096*4)   // xs0, xs1, n2h = 147456 B
#define KNN_BLOCKS 148

__global__ __launch_bounds__(1024, 1) void knn_kernel(
    const float* __restrict__ x,
    const float* __restrict__ z,
    const float* __restrict__ Wmz, const float* __restrict__ bmz,
    const float* __restrict__ Wvz, const float* __restrict__ bvz)
{
    extern __shared__ char smem_raw[];
    float4* xs0 = (float4*)smem_raw;                        // [4096]
    float4* xs1 = (float4*)(smem_raw + 4096 * 16);          // [4096]
    float*  n2h = (float*) (smem_raw + 4096 * 32);          // [4096] = n2/2

    int b = blockIdx.x & 3;
    int r = blockIdx.x >> 2;               // 0..36
    // contiguous query range: 4096 = 37*110 + 26 -> first 26 ranges get 111
    int qbase = r * 110 + (r < 26 ? r : 26);
    int qcnt  = 110 + (r < 26 ? 1 : 0);
    int npair = (qcnt + 1) >> 1;

    int tid  = threadIdx.x;
    int w    = tid >> 5;
    int lane = tid & 31;

    const float* xb = x + (b << 15);

    // stage points + exact n2 (mul + serial rn adds), stored halved
    #pragma unroll
    for (int k = 0; k < 4; k++) {
        int p = tid + (k << 10);
        float4 a = *(const float4*)(xb + p * 8);
        float4 c = *(const float4*)(xb + p * 8 + 4);
        xs0[p] = a;
        xs1[p] = c;
        float s = __fmul_rn(a.x, a.x);
        s = __fadd_rn(s, __fmul_rn(a.y, a.y));
        s = __fadd_rn(s, __fmul_rn(a.z, a.z));
        s = __fadd_rn(s, __fmul_rn(a.w, a.w));
        s = __fadd_rn(s, __fmul_rn(c.x, c.x));
        s = __fadd_rn(s, __fmul_rn(c.y, c.y));
        s = __fadd_rn(s, __fmul_rn(c.z, c.z));
        s = __fadd_rn(s, __fmul_rn(c.w, c.w));
        n2h[p] = 0.5f * s;                 // lossless halving
    }
    __syncthreads();

    // ---- folded zmix (block r==36 of each batch; bit-identical math) ----
    if (r == 36) {
        if (tid < 64) {                    // zv: this batch's 64 outputs
            int j = tid;
            float s = bvz[j];
            #pragma unroll 8
            for (int p = 0; p < 64; p++) s = fmaf(z[b * 64 + p], Wvz[p * 64 + j], s);
            g_zv[b * 64 + j] = s;
        } else if (tid < 72) {             // zm: this batch's 8 outputs
            int j = tid - 64;
            float s = bmz[j];
            #pragma unroll 8
            for (int p = 0; p < 64; p++) s = fmaf(z[b * 64 + p], Wmz[p * 8 + j], s);
            g_zm[b * 8 + j] = s;
        }
    }

    // warp-level query-pair loop (guard warp-uniform; shuffles full-mask)
    for (int qp = w; qp < npair; qp += 32) {
        int iA = qbase + 2 * qp;
        int iB = (2 * qp + 1 < qcnt) ? (iA + 1) : iA;
        float4 aA0 = xs0[iA], aA1 = xs1[iA];
        float4 aB0 = xs0[iB], aB1 = xs1[iB];

        // ---- single pass: per-lane top-8 of e-keys for both queries ----
        float A0 = FLT_MAX, A1 = FLT_MAX, A2 = FLT_MAX, A3 = FLT_MAX,
              A4 = FLT_MAX, A5 = FLT_MAX, A6 = FLT_MAX, A7 = FLT_MAX;
        float B0 = FLT_MAX, B1 = FLT_MAX, B2 = FLT_MAX, B3 = FLT_MAX,
              B4 = FLT_MAX, B5 = FLT_MAX, B6 = FLT_MAX, B7 = FLT_MAX;
        {
            int j = lane;
            #pragma unroll 1
            for (int kb = 0; kb < 32; kb++) {
                float bkA[4], bkB[4];
                #pragma unroll
                for (int c4 = 0; c4 < 4; c4++) {
                    int jj = j + (c4 << 5);
                    float4 p0 = xs0[jj];
                    float4 p1 = xs1[jj];
                    float h  = n2h[jj];
                    float eA = h;
                    eA = fmaf(-aA0.x, p0.x, eA);
                    eA = fmaf(-aA0.y, p0.y, eA);
                    eA = fmaf(-aA0.z, p0.z, eA);
                    eA = fmaf(-aA0.w, p0.w, eA);
                    eA = fmaf(-aA1.x, p1.x, eA);
                    eA = fmaf(-aA1.y, p1.y, eA);
                    eA = fmaf(-aA1.z, p1.z, eA);
                    eA = fmaf(-aA1.w, p1.w, eA);
                    bkA[c4] = __uint_as_float(
                        (__float_as_uint(eA) & 0xFFFFF000u) | (unsigned)jj);
                    float eB = h;
                    eB = fmaf(-aB0.x, p0.x, eB);
                    eB = fmaf(-aB0.y, p0.y, eB);
                    eB = fmaf(-aB0.z, p0.z, eB);
                    eB = fmaf(-aB0.w, p0.w, eB);
                    eB = fmaf(-aB1.x, p1.x, eB);
                    eB = fmaf(-aB1.y, p1.y, eB);
                    eB = fmaf(-aB1.z, p1.z, eB);
                    eB = fmaf(-aB1.w, p1.w, eB);
                    bkB[c4] = __uint_as_float(
                        (__float_as_uint(eB) & 0xFFFFF000u) | (unsigned)jj);
                }
                // query A: sort4 + partial merge + clean
                CE(bkA[0], bkA[1]); CE(bkA[2], bkA[3]);
                CE(bkA[0], bkA[2]); CE(bkA[1], bkA[3]);
                CE(bkA[1], bkA[2]);
                A4 = fminf(A4, bkA[3]);
                A5 = fminf(A5, bkA[2]);
                A6 = fminf(A6, bkA[1]);
                A7 = fminf(A7, bkA[0]);
                CE(A0, A4); CE(A1, A5); CE(A2, A6); CE(A3, A7);
                CE(A0, A2); CE(A1, A3); CE(A4, A6); CE(A5, A7);
                CE(A0, A1); CE(A2, A3); CE(A4, A5); CE(A6, A7);
                // query B: sort4 + partial merge + clean
                CE(bkB[0], bkB[1]); CE(bkB[2], bkB[3]);
                CE(bkB[0], bkB[2]); CE(bkB[1], bkB[3]);
                CE(bkB[1], bkB[2]);
                B4 = fminf(B4, bkB[3]);
                B5 = fminf(B5, bkB[2]);
                B6 = fminf(B6, bkB[1]);
                B7 = fminf(B7, bkB[0]);
                CE(B0, B4); CE(B1, B5); CE(B2, B6); CE(B3, B7);
                CE(B0, B2); CE(B1, B3); CE(B4, B6); CE(B5, B7);
                CE(B0, B1); CE(B2, B3); CE(B4, B5); CE(B6, B7);
                j += 128;
            }
        }

        // ---- per query: 20-round tournament + exact re-rank ----
        #pragma unroll 1
        for (int qq = 0; qq < 2; qq++) {
            int i = qq ? iB : iA;
            float s0 = qq ? B0 : A0, s1 = qq ? B1 : A1,
                  s2 = qq ? B2 : A2, s3 = qq ? B3 : A3,
                  s4 = qq ? B4 : A4, s5 = qq ? B5 : A5,
                  s6 = qq ? B6 : A6, s7 = qq ? B7 : A7;

            float head = s0;
            float surv = FLT_MAX;
            #pragma unroll 1
            for (int round = 0; round < 20; round++) {
                float m = head;
                m = fminf(m, __shfl_xor_sync(0xffffffffu, m, 16));
                m = fminf(m, __shfl_xor_sync(0xffffffffu, m, 8));
                m = fminf(m, __shfl_xor_sync(0xffffffffu, m, 4));
                m = fminf(m, __shfl_xor_sync(0xffffffffu, m, 2));
                m = fminf(m, __shfl_xor_sync(0xffffffffu, m, 1));
                if (round == lane) surv = m;
                unsigned bal = __ballot_sync(0xffffffffu, head == m);
                int leader = __ffs(bal) - 1;
                if (lane == leader) {
                    s0 = s1; s1 = s2; s2 = s3; s3 = s4;
                    s4 = s5; s5 = s6; s6 = s7; s7 = FLT_MAX;
                    head = s0;
                }
            }

            bool valid = (lane < 20) && (surv != FLT_MAX);
            int j = (int)(__float_as_uint(surv) & 0xFFFu);
            unsigned long long pk = 0xffffffffffffffffull;
            if (valid) {
                float4 a0 = xs0[i], a1 = xs1[i];
                float4 p0 = xs0[j], p1 = xs1[j];
                // reference-exact: serial FMA dot, (n2i+n2j)-2*dot, sqrt
                float n2i = 2.0f * n2h[i];     // lossless
                float n2j = 2.0f * n2h[j];
                float dot = __fmul_rn(a0.x, p0.x);
                dot = __fmaf_rn(a0.y, p0.y, dot);
                dot = __fmaf_rn(a0.z, p0.z, dot);
                dot = __fmaf_rn(a0.w, p0.w, dot);
                dot = __fmaf_rn(a1.x, p1.x, dot);
                dot = __fmaf_rn(a1.y, p1.y, dot);
                dot = __fmaf_rn(a1.z, p1.z, dot);
                dot = __fmaf_rn(a1.w, p1.w, dot);
                float d2 = __fsub_rn(__fadd_rn(n2i, n2j), __fmul_rn(2.0f, dot));
                float dd = sqrtf(fmaxf(d2, 0.0f));
                if (dd == 0.0f || j == i) dd = BIGF;
                pk = ((unsigned long long)__float_as_uint(dd) << 32) | (unsigned)j;
            }
            int rank = 0;
            #pragma unroll
            for (int m = 0; m < 32; m++) {
                unsigned long long o = __shfl_sync(0xffffffffu, pk, m);
                rank += (o < pk) ? 1 : 0;
            }
            if (valid && rank < 16)
                g_idx[(b * 4096 + i) * 16 + rank] = j;
        }
    }
}

// ---------------- features + fused matmuls: block per (b,n) ---------------
// R6 structure (pinned thread mapping / smem layout / feature arithmetic);
// v-matmul inner loop upgraded to packed fma.rn.f32x2 (even/odd-k split
// accumulators; mov.b64 packs elide since LDS.128 yields aligned reg pairs).
__global__ __launch_bounds__(128) void feat_kernel(
    const float* __restrict__ x,
    const float* __restrict__ Wm2, const float* __restrict__ bm2,
    const float* __restrict__ Wm3, const float* __restrict__ bm3,
    const float* __restrict__ Wv2, const float* __restrict__ bv2,
    const float* __restrict__ Wv3, const float* __restrict__ bv3,
    const float* __restrict__ Wmx, const float* __restrict__ bmx,
    const float* __restrict__ Wvx, const float* __restrict__ bvx,
    float* __restrict__ xout)
{
    int b = blockIdx.x >> 12;
    int n = blockIdx.x & 4095;
    int t = threadIdx.x;

    __shared__ __align__(16) float g[16][8];
    __shared__ __align__(16) float msm[15][32];
    __shared__ __align__(16) float vsm[15][32];
    __shared__ float mpart[8][8][15];   // [j][slice][r]
    __shared__ float xr[8][15];

    // gather 16 neighbor feature vectors
    {
        int s = t >> 3, d = t & 7;
        int nb = g_idx[(b * 4096 + n) * 16 + s] & 4095;
        g[s][d] = x[(size_t)(b * 4096 + nb) * 8 + d];
    }

    // feature-phase role
    int c   = t & 31;
    int mat = (t >> 5) & 1;
    int rh  = t >> 6;
    bool o3 = (c >= 16);
    int  k  = o3 ? (c - 16) : c;
    float w0, w1, w2 = 0.f, bb;
    if (!o3) {
        w0 = mat ? Wv2[k]      : Wm2[k];
        w1 = mat ? Wv2[16 + k] : Wm2[16 + k];
        bb = mat ? bv2[k]      : bm2[k];
    } else {
        w0 = mat ? Wv3[k]      : Wm3[k];
        w1 = mat ? Wv3[16 + k] : Wm3[16 + k];
        w2 = mat ? Wv3[32 + k] : Wm3[32 + k];
        bb = mat ? bv3[k]      : bm3[k];
    }
    __syncthreads();

    // r-invariant base: order2 p = g0*w0+b ; order3 p = g0*w0+g1*w1+b
    float p[8];
    #pragma unroll
    for (int d = 0; d < 8; d++) {
        float base = fmaf(g[0][d], w0, bb);
        p[d] = o3 ? fmaf(g[1][d], w1, base) : base;
    }
    float wlast = o3 ? w2 : w1;
    float* smo = mat ? &vsm[0][0] : &msm[0][0];

    int r0 = rh ? 8 : 0;
    int r1 = rh ? 15 : 8;
    for (int r = r0; r < r1; r++) {
        float ssum = 0.f;
        if (o3 && r == 14) {
            // tuple (0,2,3): g0*w0 + g2*w1 + g3*w2 + b
            #pragma unroll
            for (int d = 0; d < 8; d++) {
                float v = fmaf(g[3][d], w2,
                          fmaf(g[2][d], w1,
                          fmaf(g[0][d], w0, bb)));
                ssum += fmaxf(v, 0.f);
            }
        } else {
            int a = o3 ? (r + 2) : (r + 1);
            #pragma unroll
            for (int d = 0; d < 8; d++)
                ssum += fmaxf(fmaf(g[a][d], wlast, p[d]), 0.f);
        }
        smo[r * 32 + c] = ssum * 0.125f;   // mean over d (8)
    }
    __syncthreads();

    if (t < 64) {
        // v-matmul: output j=t, K=32, 15 tuples — packed f32x2 FMA
        unsigned long long acc2[15];
        #pragma unroll
        for (int r = 0; r < 15; r++) acc2[r] = 0ull;   // {0.f, 0.f}
        #pragma unroll
        for (int k4 = 0; k4 < 32; k4 += 4) {
            float q0 = Wvx[(k4 + 0) * 64 + t];
            float q1 = Wvx[(k4 + 1) * 64 + t];
            float q2 = Wvx[(k4 + 2) * 64 + t];
            float q3 = Wvx[(k4 + 3) * 64 + t];
            unsigned long long w01 = pack2(q0, q1);
            unsigned long long w23 = pack2(q2, q3);
            #pragma unroll
            for (int r = 0; r < 15; r++) {
                float4 vv = *(const float4*)&vsm[r][k4];
                ffma2(acc2[r], pack2(vv.x, vv.y), w01);
                ffma2(acc2[r], pack2(vv.z, vv.w), w23);
            }
        }
        float bias = bvx[t] + g_zv[b * 64 + t];
        float s = 0.f;
        #pragma unroll
        for (int r = 0; r < 15; r++) {
            float lo, hi;
            unpack2(acc2[r], lo, hi);
            s += fmaxf(__fadd_rn(lo, hi) + bias, 0.f);
        }
        g_zpart[(size_t)(b * 4096 + n) * 64 + t] = s;
    } else {
        // m-matmul: 8 outputs x 8 k-slices of 4
        int q = t - 64;
        int j = q >> 3;
        int sl = q & 7;
        int k0 = sl * 4;
        float q0 = Wmx[(k0 + 0) * 8 + j];
        float q1 = Wmx[(k0 + 1) * 8 + j];
        float q2 = Wmx[(k0 + 2) * 8 + j];
        float q3 = Wmx[(k0 + 3) * 8 + j];
        #pragma unroll
        for (int r = 0; r < 15; r++) {
            float4 mv = *(const float4*)&msm[r][k0];
            float a = mv.x * q0;
            a = fmaf(mv.y, q1, a);
            a = fmaf(mv.z, q2, a);
            a = fmaf(mv.w, q3, a);
            mpart[j][sl][r] = a;
        }
    }
    __syncthreads();

    if (t < 120) {
        int j = t / 15, r = t % 15;
        float s = 0.f;
        #pragma unroll
        for (int sl = 0; sl < 8; sl++) s += mpart[j][sl][r];
        xr[j][r] = fmaxf(s + bmx[j] + g_zm[b * 8 + j], 0.f);
    }
    __syncthreads();
    if (t < 8) {
        float s = 0.f;
        #pragma unroll
        for (int r = 0; r < 15; r++) s += xr[t][r];
        xout[(size_t)b * 32768 + n * 8 + t] = s * (1.f / 15.f);
    }
}

// ---------------- z reduction, two-stage ----------------------------------
__global__ __launch_bounds__(256) void zred1_kernel()
{
    int b = blockIdx.x >> 6;
    int c = blockIdx.x & 63;
    int t = threadIdx.x;
    int q = t >> 6, j = t & 63;
    const float* zp = g_zpart + ((size_t)(b * 4096 + c * 64) * 64);
    float s = 0.f;
    #pragma unroll 16
    for (int k = q * 16; k < q * 16 + 16; k++) s += zp[k * 64 + j];
    __shared__ float red[256];
    red[t] = s;
    __syncthreads();
    if (t < 64)
        g_zp2[(b * 64 + c) * 64 + t] =
            red[t] + red[t + 64] + red[t + 128] + red[t + 192];
}

__global__ __launch_bounds__(64) void zred2_kernel(float* __restrict__ out)
{
    int b = blockIdx.x;
    int j = threadIdx.x;
    float s = 0.f;
    #pragma unroll 8
    for (int c = 0; c < 64; c++) s += g_zp2[(b * 64 + c) * 64 + j];
    out[131072 + b * 64 + j] = s * (1.f / 61440.f);
}

// ---------------- launch ---------------------------------------------------
extern "C" void kernel_launch(void* const* d_in, const int* in_sizes, int n_in,
                              void* d_out, int out_size)
{
    const float* x   = (const float*)d_in[0];
    const float* z   = (const float*)d_in[1];
    const float* Wm2 = (const float*)d_in[2];
    const float* bm2 = (const float*)d_in[3];
    const float* Wm3 = (const float*)d_in[4];
    const float* bm3 = (const float*)d_in[5];
    const float* Wv2 = (const float*)d_in[6];
    const float* bv2 = (const float*)d_in[7];
    const float* Wv3 = (const float*)d_in[8];
    const float* bv3 = (const float*)d_in[9];
    const float* Wmx = (const float*)d_in[10];
    const float* bmx = (const float*)d_in[11];
    const float* Wvx = (const float*)d_in[12];
    const float* bvx = (const float*)d_in[13];
    const float* Wmz = (const float*)d_in[14];
    const float* bmz = (const float*)d_in[15];
    const float* Wvz = (const float*)d_in[16];
    const float* bvz = (const float*)d_in[17];
    float* out = (float*)d_out;

    cudaFuncSetAttribute(knn_kernel,
                         cudaFuncAttributeMaxDynamicSharedMemorySize, KNN_SMEM);

    knn_kernel<<<KNN_BLOCKS, 1024, KNN_SMEM>>>(x, z, Wmz, bmz, Wvz, bvz);
    feat_kernel<<<16384, 128>>>(x,
                                Wm2, bm2, Wm3, bm3, Wv2, bv2, Wv3, bv3,
                                Wmx, bmx, Wvx, bvx, out);
    zred1_kernel<<<256, 256>>>();
    zred2_kernel<<<4, 64>>>(out);
}

// round 16
// speedup vs baseline: 2.4094x; 1.0102x over previous
#include <cuda_runtime.h>
#include <cuda_bf16.h>
#include <math.h>
#include <float.h>

// Shapes (fixed): B=4, NP=4096, D_FEAT=8, N=16, DM=16, DO=8, NM=64, PNM=64
#define BIGF 99999999.0f

// ---------------- scratch (__device__ globals) ----------------------------
__device__ int   g_idx[4 * 4096 * 16];      // knn indices, ascending-distance order
__device__ float g_zpart[4 * 4096 * 64];    // per-(b,n) z partial sums
__device__ float g_zp2[4 * 128 * 64];       // stage-1 z reduction partials
__device__ float g_zm[4 * 8];               // z @ Wmz + bmz
__device__ float g_zv[4 * 64];              // z @ Wvz + bvz

#define CE(a, b) { float _mn = fminf(a, b); b = fmaxf(a, b); a = _mn; }

__device__ __forceinline__ unsigned long long pack2(float a, float b) {
    unsigned long long r;
    asm("mov.b64 %0, {%1, %2};" : "=l"(r) : "f"(a), "f"(b));
    return r;
}
__device__ __forceinline__ void unpack2(unsigned long long v, float& a, float& b) {
    asm("mov.b64 {%0, %1}, %2;" : "=f"(a), "=f"(b) : "l"(v));
}
__device__ __forceinline__ void ffma2(unsigned long long& acc,
                                      unsigned long long ab, unsigned long long cd) {
    asm("fma.rn.f32x2 %0, %1, %2, %0;" : "+l"(acc) : "l"(ab), "l"(cd));
}

// ---------------- kNN: persistent, 2 queries/warp, batched bitonic --------
// (R14/R15 selection path — bit-identical output; pinned.)
#define KNN_SMEM (4096*16*2 + 4096*4)   // xs0, xs1, n2h = 147456 B
#define KNN_BLOCKS 148

__global__ __launch_bounds__(1024, 1) void knn_kernel(
    const float* __restrict__ x,
    const float* __restrict__ z,
    const float* __restrict__ Wmz, const float* __restrict__ bmz,
    const float* __restrict__ Wvz, const float* __restrict__ bvz)
{
    extern __shared__ char smem_raw[];
    float4* xs0 = (float4*)smem_raw;                        // [4096]
    float4* xs1 = (float4*)(smem_raw + 4096 * 16);          // [4096]
    float*  n2h = (float*) (smem_raw + 4096 * 32);          // [4096] = n2/2

    int b = blockIdx.x & 3;
    int r = blockIdx.x >> 2;               // 0..36
    // contiguous query range: 4096 = 37*110 + 26 -> first 26 ranges get 111
    int qbase = r * 110 + (r < 26 ? r : 26);
    int qcnt  = 110 + (r < 26 ? 1 : 0);
    int npair = (qcnt + 1) >> 1;

    int tid  = threadIdx.x;
    int w    = tid >> 5;
    int lane = tid & 31;

    const float* xb = x + (b << 15);

    // stage points + exact n2 (mul + serial rn adds), stored halved
    #pragma unroll
    for (int k = 0; k < 4; k++) {
        int p = tid + (k << 10);
        float4 a = *(const float4*)(xb + p * 8);
        float4 c = *(const float4*)(xb + p * 8 + 4);
        xs0[p] = a;
        xs1[p] = c;
        float s = __fmul_rn(a.x, a.x);
        s = __fadd_rn(s, __fmul_rn(a.y, a.y));
        s = __fadd_rn(s, __fmul_rn(a.z, a.z));
        s = __fadd_rn(s, __fmul_rn(a.w, a.w));
        s = __fadd_rn(s, __fmul_rn(c.x, c.x));
        s = __fadd_rn(s, __fmul_rn(c.y, c.y));
        s = __fadd_rn(s, __fmul_rn(c.z, c.z));
        s = __fadd_rn(s, __fmul_rn(c.w, c.w));
        n2h[p] = 0.5f * s;                 // lossless halving
    }
    __syncthreads();

    // ---- folded zmix (block r==36 of each batch; bit-identical math) ----
    if (r == 36) {
        if (tid < 64) {                    // zv: this batch's 64 outputs
            int j = tid;
            float s = bvz[j];
            #pragma unroll 8
            for (int p = 0; p < 64; p++) s = fmaf(z[b * 64 + p], Wvz[p * 64 + j], s);
            g_zv[b * 64 + j] = s;
        } else if (tid < 72) {             // zm: this batch's 8 outputs
            int j = tid - 64;
            float s = bmz[j];
            #pragma unroll 8
            for (int p = 0; p < 64; p++) s = fmaf(z[b * 64 + p], Wmz[p * 8 + j], s);
            g_zm[b * 8 + j] = s;
        }
    }

    // warp-level query-pair loop (guard warp-uniform; shuffles full-mask)
    for (int qp = w; qp < npair; qp += 32) {
        int iA = qbase + 2 * qp;
        int iB = (2 * qp + 1 < qcnt) ? (iA + 1) : iA;
        float4 aA0 = xs0[iA], aA1 = xs1[iA];
        float4 aB0 = xs0[iB], aB1 = xs1[iB];

        // ---- single pass: per-lane top-8 of e-keys for both queries ----
        float A0 = FLT_MAX, A1 = FLT_MAX, A2 = FLT_MAX, A3 = FLT_MAX,
              A4 = FLT_MAX, A5 = FLT_MAX, A6 = FLT_MAX, A7 = FLT_MAX;
        float B0 = FLT_MAX, B1 = FLT_MAX, B2 = FLT_MAX, B3 = FLT_MAX,
              B4 = FLT_MAX, B5 = FLT_MAX, B6 = FLT_MAX, B7 = FLT_MAX;
        {
            int j = lane;
            #pragma unroll 1
            for (int kb = 0; kb < 32; kb++) {
                float bkA[4], bkB[4];
                #pragma unroll
                for (int c4 = 0; c4 < 4; c4++) {
                    int jj = j + (c4 << 5);
                    float4 p0 = xs0[jj];
                    float4 p1 = xs1[jj];
                    float h  = n2h[jj];
                    float eA = h;
                    eA = fmaf(-aA0.x, p0.x, eA);
                    eA = fmaf(-aA0.y, p0.y, eA);
                    eA = fmaf(-aA0.z, p0.z, eA);
                    eA = fmaf(-aA0.w, p0.w, eA);
                    eA = fmaf(-aA1.x, p1.x, eA);
                    eA = fmaf(-aA1.y, p1.y, eA);
                    eA = fmaf(-aA1.z, p1.z, eA);
                    eA = fmaf(-aA1.w, p1.w, eA);
                    bkA[c4] = __uint_as_float(
                        (__float_as_uint(eA) & 0xFFFFF000u) | (unsigned)jj);
                    float eB = h;
                    eB = fmaf(-aB0.x, p0.x, eB);
                    eB = fmaf(-aB0.y, p0.y, eB);
                    eB = fmaf(-aB0.z, p0.z, eB);
                    eB = fmaf(-aB0.w, p0.w, eB);
                    eB = fmaf(-aB1.x, p1.x, eB);
                    eB = fmaf(-aB1.y, p1.y, eB);
                    eB = fmaf(-aB1.z, p1.z, eB);
                    eB = fmaf(-aB1.w, p1.w, eB);
                    bkB[c4] = __uint_as_float(
                        (__float_as_uint(eB) & 0xFFFFF000u) | (unsigned)jj);
                }
                // query A: sort4 + partial merge + clean
                CE(bkA[0], bkA[1]); CE(bkA[2], bkA[3]);
                CE(bkA[0], bkA[2]); CE(bkA[1], bkA[3]);
                CE(bkA[1], bkA[2]);
                A4 = fminf(A4, bkA[3]);
                A5 = fminf(A5, bkA[2]);
                A6 = fminf(A6, bkA[1]);
                A7 = fminf(A7, bkA[0]);
                CE(A0, A4); CE(A1, A5); CE(A2, A6); CE(A3, A7);
                CE(A0, A2); CE(A1, A3); CE(A4, A6); CE(A5, A7);
                CE(A0, A1); CE(A2, A3); CE(A4, A5); CE(A6, A7);
                // query B: sort4 + partial merge + clean
                CE(bkB[0], bkB[1]); CE(bkB[2], bkB[3]);
                CE(bkB[0], bkB[2]); CE(bkB[1], bkB[3]);
                CE(bkB[1], bkB[2]);
                B4 = fminf(B4, bkB[3]);
                B5 = fminf(B5, bkB[2]);
                B6 = fminf(B6, bkB[1]);
                B7 = fminf(B7, bkB[0]);
                CE(B0, B4); CE(B1, B5); CE(B2, B6); CE(B3, B7);
                CE(B0, B2); CE(B1, B3); CE(B4, B6); CE(B5, B7);
                CE(B0, B1); CE(B2, B3); CE(B4, B5); CE(B6, B7);
                j += 128;
            }
        }

        // ---- per query: 20-round tournament + exact re-rank ----
        #pragma unroll 1
        for (int qq = 0; qq < 2; qq++) {
            int i = qq ? iB : iA;
            float s0 = qq ? B0 : A0, s1 = qq ? B1 : A1,
                  s2 = qq ? B2 : A2, s3 = qq ? B3 : A3,
                  s4 = qq ? B4 : A4, s5 = qq ? B5 : A5,
                  s6 = qq ? B6 : A6, s7 = qq ? B7 : A7;

            float head = s0;
            float surv = FLT_MAX;
            #pragma unroll 1
            for (int round = 0; round < 20; round++) {
                float m = head;
                m = fminf(m, __shfl_xor_sync(0xffffffffu, m, 16));
                m = fminf(m, __shfl_xor_sync(0xffffffffu, m, 8));
                m = fminf(m, __shfl_xor_sync(0xffffffffu, m, 4));
                m = fminf(m, __shfl_xor_sync(0xffffffffu, m, 2));
                m = fminf(m, __shfl_xor_sync(0xffffffffu, m, 1));
                if (round == lane) surv = m;
                unsigned bal = __ballot_sync(0xffffffffu, head == m);
                int leader = __ffs(bal) - 1;
                if (lane == leader) {
                    s0 = s1; s1 = s2; s2 = s3; s3 = s4;
                    s4 = s5; s5 = s6; s6 = s7; s7 = FLT_MAX;
                    head = s0;
                }
            }

            bool valid = (lane < 20) && (surv != FLT_MAX);
            int j = (int)(__float_as_uint(surv) & 0xFFFu);
            unsigned long long pk = 0xffffffffffffffffull;
            if (valid) {
                float4 a0 = xs0[i], a1 = xs1[i];
                float4 p0 = xs0[j], p1 = xs1[j];
                // reference-exact: serial FMA dot, (n2i+n2j)-2*dot, sqrt
                float n2i = 2.0f * n2h[i];     // lossless
                float n2j = 2.0f * n2h[j];
                float dot = __fmul_rn(a0.x, p0.x);
                dot = __fmaf_rn(a0.y, p0.y, dot);
                dot = __fmaf_rn(a0.z, p0.z, dot);
                dot = __fmaf_rn(a0.w, p0.w, dot);
                dot = __fmaf_rn(a1.x, p1.x, dot);
                dot = __fmaf_rn(a1.y, p1.y, dot);
                dot = __fmaf_rn(a1.z, p1.z, dot);
                dot = __fmaf_rn(a1.w, p1.w, dot);
                float d2 = __fsub_rn(__fadd_rn(n2i, n2j), __fmul_rn(2.0f, dot));
                float dd = sqrtf(fmaxf(d2, 0.0f));
                if (dd == 0.0f || j == i) dd = BIGF;
                pk = ((unsigned long long)__float_as_uint(dd) << 32) | (unsigned)j;
            }
            int rank = 0;
            #pragma unroll
            for (int m = 0; m < 32; m++) {
                unsigned long long o = __shfl_sync(0xffffffffu, pk, m);
                rank += (o < pk) ? 1 : 0;
            }
            if (valid && rank < 16)
                g_idx[(b * 4096 + i) * 16 + rank] = j;
        }
    }
}

// ---------------- features + fused matmuls: block per (b,n) ---------------
// (R15 version — pinned.)
__global__ __launch_bounds__(128) void feat_kernel(
    const float* __restrict__ x,
    const float* __restrict__ Wm2, const float* __restrict__ bm2,
    const float* __restrict__ Wm3, const float* __restrict__ bm3,
    const float* __restrict__ Wv2, const float* __restrict__ bv2,
    const float* __restrict__ Wv3, const float* __restrict__ bv3,
    const float* __restrict__ Wmx, const float* __restrict__ bmx,
    const float* __restrict__ Wvx, const float* __restrict__ bvx,
    float* __restrict__ xout)
{
    int b = blockIdx.x >> 12;
    int n = blockIdx.x & 4095;
    int t = threadIdx.x;

    __shared__ __align__(16) float g[16][8];
    __shared__ __align__(16) float msm[15][32];
    __shared__ __align__(16) float vsm[15][32];
    __shared__ float mpart[8][8][15];   // [j][slice][r]
    __shared__ float xr[8][15];

    // gather 16 neighbor feature vectors
    {
        int s = t >> 3, d = t & 7;
        int nb = g_idx[(b * 4096 + n) * 16 + s] & 4095;
        g[s][d] = x[(size_t)(b * 4096 + nb) * 8 + d];
    }

    // feature-phase role
    int c   = t & 31;
    int mat = (t >> 5) & 1;
    int rh  = t >> 6;
    bool o3 = (c >= 16);
    int  k  = o3 ? (c - 16) : c;
    float w0, w1, w2 = 0.f, bb;
    if (!o3) {
        w0 = mat ? Wv2[k]      : Wm2[k];
        w1 = mat ? Wv2[16 + k] : Wm2[16 + k];
        bb = mat ? bv2[k]      : bm2[k];
    } else {
        w0 = mat ? Wv3[k]      : Wm3[k];
        w1 = mat ? Wv3[16 + k] : Wm3[16 + k];
        w2 = mat ? Wv3[32 + k] : Wm3[32 + k];
        bb = mat ? bv3[k]      : bm3[k];
    }
    __syncthreads();

    // r-invariant base: order2 p = g0*w0+b ; order3 p = g0*w0+g1*w1+b
    float p[8];
    #pragma unroll
    for (int d = 0; d < 8; d++) {
        float base = fmaf(g[0][d], w0, bb);
        p[d] = o3 ? fmaf(g[1][d], w1, base) : base;
    }
    float wlast = o3 ? w2 : w1;
    float* smo = mat ? &vsm[0][0] : &msm[0][0];

    int r0 = rh ? 8 : 0;
    int r1 = rh ? 15 : 8;
    for (int r = r0; r < r1; r++) {
        float ssum = 0.f;
        if (o3 && r == 14) {
            // tuple (0,2,3): g0*w0 + g2*w1 + g3*w2 + b
            #pragma unroll
            for (int d = 0; d < 8; d++) {
                float v = fmaf(g[3][d], w2,
                          fmaf(g[2][d], w1,
                          fmaf(g[0][d], w0, bb)));
                ssum += fmaxf(v, 0.f);
            }
        } else {
            int a = o3 ? (r + 2) : (r + 1);
            #pragma unroll
            for (int d = 0; d < 8; d++)
                ssum += fmaxf(fmaf(g[a][d], wlast, p[d]), 0.f);
        }
        smo[r * 32 + c] = ssum * 0.125f;   // mean over d (8)
    }
    __syncthreads();

    if (t < 64) {
        // v-matmul: output j=t, K=32, 15 tuples — packed f32x2 FMA
        unsigned long long acc2[15];
        #pragma unroll
        for (int r = 0; r < 15; r++) acc2[r] = 0ull;   // {0.f, 0.f}
        #pragma unroll
        for (int k4 = 0; k4 < 32; k4 += 4) {
            float q0 = Wvx[(k4 + 0) * 64 + t];
            float q1 = Wvx[(k4 + 1) * 64 + t];
            float q2 = Wvx[(k4 + 2) * 64 + t];
            float q3 = Wvx[(k4 + 3) * 64 + t];
            unsigned long long w01 = pack2(q0, q1);
            unsigned long long w23 = pack2(q2, q3);
            #pragma unroll
            for (int r = 0; r < 15; r++) {
                float4 vv = *(const float4*)&vsm[r][k4];
                ffma2(acc2[r], pack2(vv.x, vv.y), w01);
                ffma2(acc2[r], pack2(vv.z, vv.w), w23);
            }
        }
        float bias = bvx[t] + g_zv[b * 64 + t];
        float s = 0.f;
        #pragma unroll
        for (int r = 0; r < 15; r++) {
            float lo, hi;
            unpack2(acc2[r], lo, hi);
            s += fmaxf(__fadd_rn(lo, hi) + bias, 0.f);
        }
        g_zpart[(size_t)(b * 4096 + n) * 64 + t] = s;
    } else {
        // m-matmul: 8 outputs x 8 k-slices of 4
        int q = t - 64;
        int j = q >> 3;
        int sl = q & 7;
        int k0 = sl * 4;
        float q0 = Wmx[(k0 + 0) * 8 + j];
        float q1 = Wmx[(k0 + 1) * 8 + j];
        float q2 = Wmx[(k0 + 2) * 8 + j];
        float q3 = Wmx[(k0 + 3) * 8 + j];
        #pragma unroll
        for (int r = 0; r < 15; r++) {
            float4 mv = *(const float4*)&msm[r][k0];
            float a = mv.x * q0;
            a = fmaf(mv.y, q1, a);
            a = fmaf(mv.z, q2, a);
            a = fmaf(mv.w, q3, a);
            mpart[j][sl][r] = a;
        }
    }
    __syncthreads();

    if (t < 120) {
        int j = t / 15, r = t % 15;
        float s = 0.f;
        #pragma unroll
        for (int sl = 0; sl < 8; sl++) s += mpart[j][sl][r];
        xr[j][r] = fmaxf(s + bmx[j] + g_zm[b * 8 + j], 0.f);
    }
    __syncthreads();
    if (t < 8) {
        float s = 0.f;
        #pragma unroll
        for (int r = 0; r < 15; r++) s += xr[t][r];
        xout[(size_t)b * 32768 + n * 8 + t] = s * (1.f / 15.f);
    }
}

// ---------------- z reduction, two-stage (widened) ------------------------
// stage 1: 512 blocks, each reduces a 32-row chunk of g_zpart (4-way k-split
// per j + smem combine) -> g_zp2[4][128][64]
__global__ __launch_bounds__(256) void zred1_kernel()
{
    int b = blockIdx.x >> 7;
    int c = blockIdx.x & 127;              // 32-row chunk
    int t = threadIdx.x;
    int q = t >> 6, j = t & 63;            // q: 8-row subchunk
    const float* zp = g_zpart + ((size_t)(b * 4096 + c * 32) * 64);
    float s = 0.f;
    #pragma unroll 8
    for (int k = q * 8; k < q * 8 + 8; k++) s += zp[k * 64 + j];
    __shared__ float red[256];
    red[t] = s;
    __syncthreads();
    if (t < 64)
        g_zp2[(b * 128 + c) * 64 + t] =
            red[t] + red[t + 64] + red[t + 128] + red[t + 192];
}

// stage 2: 4 blocks x 256 threads; 4-way c-split per j + smem combine
__global__ __launch_bounds__(256) void zred2_kernel(float* __restrict__ out)
{
    int b = blockIdx.x;
    int t = threadIdx.x;
    int q = t >> 6, j = t & 63;
    float s = 0.f;
    #pragma unroll 8
    for (int c = q * 32; c < q * 32 + 32; c++)
        s += g_zp2[(b * 128 + c) * 64 + j];
    __shared__ float red[256];
    red[t] = s;
    __syncthreads();
    if (t < 64)
        out[131072 + b * 64 + t] =
            (red[t] + red[t + 64] + red[t + 128] + red[t + 192]) * (1.f / 61440.f);
}

// ---------------- launch ---------------------------------------------------
extern "C" void kernel_launch(void* const* d_in, const int* in_sizes, int n_in,
                              void* d_out, int out_size)
{
    const float* x   = (const float*)d_in[0];
    const float* z   = (const float*)d_in[1];
    const float* Wm2 = (const float*)d_in[2];
    const float* bm2 = (const float*)d_in[3];
    const float* Wm3 = (const float*)d_in[4];
    const float* bm3 = (const float*)d_in[5];
    const float* Wv2 = (const float*)d_in[6];
    const float* bv2 = (const float*)d_in[7];
    const float* Wv3 = (const float*)d_in[8];
    const float* bv3 = (const float*)d_in[9];
    const float* Wmx = (const float*)d_in[10];
    const float* bmx = (const float*)d_in[11];
    const float* Wvx = (const float*)d_in[12];
    const float* bvx = (const float*)d_in[13];
    const float* Wmz = (const float*)d_in[14];
    const float* bmz = (const float*)d_in[15];
    const float* Wvz = (const float*)d_in[16];
    const float* bvz = (const float*)d_in[17];
    float* out = (float*)d_out;

    cudaFuncSetAttribute(knn_kernel,
                         cudaFuncAttributeMaxDynamicSharedMemorySize, KNN_SMEM);

    knn_kernel<<<KNN_BLOCKS, 1024, KNN_SMEM>>>(x, z, Wmz, bmz, Wvz, bvz);
    feat_kernel<<<16384, 128>>>(x,
                                Wm2, bm2, Wm3, bm3, Wv2, bv2, Wv3, bv3,
                                Wmx, bmx, Wvx, bvx, out);
    zred1_kernel<<<512, 256>>>();
    zred2_kernel<<<4, 256>>>(out);
}